// round 1
// baseline (speedup 1.0000x reference)
#include <cuda_runtime.h>
#include <cstdint>
#include <cstddef>

// Problem constants
#define B_ 4
#define T_ 2048
#define KD_ 128
#define H_ 8
#define C_ 1024   // KD_*H_

// Scratch (device globals; no allocation allowed)
__device__ float g_Q[(size_t)B_*T_*H_*KD_];
__device__ float g_K[(size_t)B_*T_*H_*KD_];
__device__ float g_V[(size_t)B_*T_*H_*KD_];
__device__ float g_P[(size_t)B_*T_*H_*KD_];

// ---------------------------------------------------------------------------
// Generic conv-as-GEMM kernel.
// out(b,t,c) = silu( bias[c] + sum_{cin,j} W[c][cin][j] * X[b][t + j*DILT - PADT][cin] ) * scale
// Tile: 32 t x 128 c per CTA, 256 threads, 4x4 per thread.
// REMAP=true stores to [b][t][h=c%8][k=c/8] layout (for Q/K/V).
// ---------------------------------------------------------------------------
template<int NTAPS, int DILT, int PADT, int CIN, int CI, int CTOT, bool BIAS, bool REMAP>
__global__ void __launch_bounds__(256) conv_gemm_kernel(
    const float* __restrict__ X, const float* __restrict__ W,
    const float* __restrict__ bias, float* __restrict__ out, float scale)
{
    constexpr int TT = 32, TC = 128;
    constexpr int II = CI * NTAPS;
    constexpr int NROWS = TT + DILT * (NTAPS - 1);

    __shared__ float Xs[NROWS][CI + 1];
    __shared__ float Ws[II][TC];

    const int t0 = blockIdx.x * TT;
    const int c0 = blockIdx.y * TC;
    const int b  = blockIdx.z;
    const int tid = threadIdx.x;
    const int ct = tid & 31;   // c group: channels ct*4 .. ct*4+3
    const int tt = tid >> 5;   // t group: times   tt*4 .. tt*4+3

    float acc[4][4] = {};

    for (int cin0 = 0; cin0 < CIN; cin0 += CI) {
        __syncthreads();
        // ---- load X tile (rows t0-PADT .. t0+TT-1+span, cols cin0..cin0+CI-1)
        for (int idx = tid; idx < NROWS * CI; idx += 256) {
            int r  = idx / CI;
            int cc = idx - r * CI;
            int tg = t0 + r - PADT;
            float v = 0.0f;
            if (tg >= 0 && tg < T_)
                v = X[((size_t)b * T_ + tg) * CIN + cin0 + cc];
            Xs[r][cc] = v;
        }
        // ---- load W tile: Ws[i][c], i = cin_local*NTAPS + j (contiguous in global W)
        {
            int c = tid >> 1, half = tid & 1;
            const float* wp = W + ((size_t)(c0 + c) * CIN + cin0) * NTAPS + half * (II / 2);
            #pragma unroll
            for (int k2 = 0; k2 < II / 2; k2++)
                Ws[half * (II / 2) + k2][c] = wp[k2];
        }
        __syncthreads();

        // ---- compute
        #pragma unroll 2
        for (int cinl = 0; cinl < CI; cinl++) {
            #pragma unroll
            for (int j = 0; j < NTAPS; j++) {
                const int i = cinl * NTAPS + j;
                const int rb = tt * 4 + j * DILT;
                float a0 = Xs[rb + 0][cinl];
                float a1 = Xs[rb + 1][cinl];
                float a2 = Xs[rb + 2][cinl];
                float a3 = Xs[rb + 3][cinl];
                float4 bb = *(const float4*)&Ws[i][ct * 4];
                acc[0][0] += a0 * bb.x; acc[0][1] += a0 * bb.y; acc[0][2] += a0 * bb.z; acc[0][3] += a0 * bb.w;
                acc[1][0] += a1 * bb.x; acc[1][1] += a1 * bb.y; acc[1][2] += a1 * bb.z; acc[1][3] += a1 * bb.w;
                acc[2][0] += a2 * bb.x; acc[2][1] += a2 * bb.y; acc[2][2] += a2 * bb.z; acc[2][3] += a2 * bb.w;
                acc[3][0] += a3 * bb.x; acc[3][1] += a3 * bb.y; acc[3][2] += a3 * bb.z; acc[3][3] += a3 * bb.w;
            }
        }
    }

    // ---- epilogue: bias + silu + scale + store
    #pragma unroll
    for (int cc = 0; cc < 4; cc++) {
        const int c = c0 + ct * 4 + cc;
        const float bv = BIAS ? bias[c] : 0.0f;
        #pragma unroll
        for (int tv = 0; tv < 4; tv++) {
            const int t = t0 + tt * 4 + tv;
            float y = acc[tv][cc] + bv;
            float s = y / (1.0f + __expf(-y));
            s *= scale;
            size_t o;
            if (REMAP) {
                // channel c = ko*H + h  ->  [b][t][h][ko]
                o = (((size_t)b * T_ + t) * H_ + (c & 7)) * KD_ + (c >> 3);
            } else {
                o = ((size_t)b * T_ + t) * CTOT + c;
            }
            out[o] = s;
        }
    }
}

// ---------------------------------------------------------------------------
// Flash attention (fp32), causal, per (m, q-tile). BM=BN=64, D=128, 256 thr.
// Q/K/V flat [32][2048][128] views over [b][t][h][k] buffers.
// Output written to [b][t][h][k] layout (t = attention position s).
// Dynamic smem layout (floats):
//   Qt [128][68] transposed | uni: K-transposed [128][68] OR V [64][128]
//   Ps [64][65] | m_sh[64] | l_sh[64] | al_sh[64]
// ---------------------------------------------------------------------------
#define QT_STRIDE 68
#define PS_STRIDE 65
#define ATTN_SMEM_FLOATS (128*QT_STRIDE + 128*QT_STRIDE + 64*PS_STRIDE + 192)

__global__ void __launch_bounds__(256) attn_kernel(
    const float* __restrict__ Qb, const float* __restrict__ Kb,
    const float* __restrict__ Vb, float* __restrict__ P)
{
    extern __shared__ float sm[];
    float* Qt    = sm;
    float* uni   = sm + 128 * QT_STRIDE;
    float* Ps    = uni + 128 * QT_STRIDE;
    float* m_sh  = Ps + 64 * PS_STRIDE;
    float* l_sh  = m_sh + 64;
    float* al_sh = l_sh + 64;

    const int tid = threadIdx.x;
    const int m   = blockIdx.y;
    const int qi  = (int)gridDim.x - 1 - (int)blockIdx.x;  // heavy tiles first
    const int q0  = qi * 64;
    const size_t mbase = (size_t)m * T_ * KD_;

    if (tid < 64) { m_sh[tid] = -3.0e38f; l_sh[tid] = 0.0f; }

    // load Q tile transposed: Qt[d][s]
    {
        const int s = tid & 63, qq = tid >> 6;
        const float* src = Qb + mbase + (size_t)(q0 + s) * KD_;
        #pragma unroll
        for (int it = 0; it < 8; it++) {
            const int d0 = (qq * 8 + it) * 4;
            float4 f = *(const float4*)(src + d0);
            Qt[(d0 + 0) * QT_STRIDE + s] = f.x;
            Qt[(d0 + 1) * QT_STRIDE + s] = f.y;
            Qt[(d0 + 2) * QT_STRIDE + s] = f.z;
            Qt[(d0 + 3) * QT_STRIDE + s] = f.w;
        }
    }

    float o[4][8] = {};
    const int ry = tid & 15, cx = tid >> 4;  // S phase: rows 4ry.., cols 4cx..
    const int dg = tid & 15, rg = tid >> 4;  // PV phase: rows 4rg.., cols 8dg..

    const int ntiles = qi + 1;
    for (int kt = 0; kt < ntiles; kt++) {
        const int s0 = kt * 64;
        __syncthreads();
        // ---- load K tile transposed into uni
        {
            const int s = tid & 63, qq = tid >> 6;
            const float* src = Kb + mbase + (size_t)(s0 + s) * KD_;
            #pragma unroll
            for (int it = 0; it < 8; it++) {
                const int d0 = (qq * 8 + it) * 4;
                float4 f = *(const float4*)(src + d0);
                uni[(d0 + 0) * QT_STRIDE + s] = f.x;
                uni[(d0 + 1) * QT_STRIDE + s] = f.y;
                uni[(d0 + 2) * QT_STRIDE + s] = f.z;
                uni[(d0 + 3) * QT_STRIDE + s] = f.w;
            }
        }
        __syncthreads();
        // ---- S = Q K^T
        float acc[4][4] = {};
        #pragma unroll 8
        for (int kk = 0; kk < 128; kk++) {
            float4 a  = *(const float4*)&Qt[kk * QT_STRIDE + ry * 4];
            float4 bb = *(const float4*)&uni[kk * QT_STRIDE + cx * 4];
            acc[0][0] += a.x * bb.x; acc[0][1] += a.x * bb.y; acc[0][2] += a.x * bb.z; acc[0][3] += a.x * bb.w;
            acc[1][0] += a.y * bb.x; acc[1][1] += a.y * bb.y; acc[1][2] += a.y * bb.z; acc[1][3] += a.y * bb.w;
            acc[2][0] += a.z * bb.x; acc[2][1] += a.z * bb.y; acc[2][2] += a.z * bb.z; acc[2][3] += a.z * bb.w;
            acc[3][0] += a.w * bb.x; acc[3][1] += a.w * bb.y; acc[3][2] += a.w * bb.z; acc[3][3] += a.w * bb.w;
        }
        const bool diag = (s0 == q0);
        #pragma unroll
        for (int ri = 0; ri < 4; ri++) {
            #pragma unroll
            for (int ci = 0; ci < 4; ci++) {
                float v = acc[ri][ci];
                if (diag && (cx * 4 + ci) > (ry * 4 + ri)) v = -1.0e30f;
                Ps[(ry * 4 + ri) * PS_STRIDE + cx * 4 + ci] = v;
            }
        }
        __syncthreads();
        // ---- load V into uni (K no longer needed) + online softmax on Ps
        {
            float4* dst = (float4*)uni;
            const float4* src = (const float4*)(Vb + mbase + (size_t)s0 * KD_);
            #pragma unroll
            for (int it = 0; it < 8; it++) dst[it * 256 + tid] = src[it * 256 + tid];
        }
        {
            const int r = tid >> 2, part = tid & 3;
            float* prow = &Ps[r * PS_STRIDE + part * 16];
            float vals[16];
            float mx = -3.0e38f;
            #pragma unroll
            for (int c2 = 0; c2 < 16; c2++) { vals[c2] = prow[c2]; mx = fmaxf(mx, vals[c2]); }
            mx = fmaxf(mx, __shfl_xor_sync(0xffffffffu, mx, 1));
            mx = fmaxf(mx, __shfl_xor_sync(0xffffffffu, mx, 2));
            const float mold = m_sh[r];
            const float mnew = fmaxf(mold, mx);
            float sum = 0.0f;
            #pragma unroll
            for (int c2 = 0; c2 < 16; c2++) {
                float p = __expf(vals[c2] - mnew);
                prow[c2] = p;
                sum += p;
            }
            sum += __shfl_xor_sync(0xffffffffu, sum, 1);
            sum += __shfl_xor_sync(0xffffffffu, sum, 2);
            if (part == 0) {
                const float alpha = __expf(mold - mnew);
                m_sh[r]  = mnew;
                al_sh[r] = alpha;
                l_sh[r]  = l_sh[r] * alpha + sum;
            }
        }
        __syncthreads();
        // ---- O = O*alpha + P V
        #pragma unroll
        for (int i = 0; i < 4; i++) {
            const float al = al_sh[rg * 4 + i];
            #pragma unroll
            for (int e = 0; e < 8; e++) o[i][e] *= al;
        }
        #pragma unroll 4
        for (int s = 0; s < 64; s++) {
            float4 v0 = *(const float4*)&uni[s * KD_ + dg * 8];
            float4 v1 = *(const float4*)&uni[s * KD_ + dg * 8 + 4];
            #pragma unroll
            for (int i = 0; i < 4; i++) {
                const float a = Ps[(rg * 4 + i) * PS_STRIDE + s];
                o[i][0] += a * v0.x; o[i][1] += a * v0.y; o[i][2] += a * v0.z; o[i][3] += a * v0.w;
                o[i][4] += a * v1.x; o[i][5] += a * v1.y; o[i][6] += a * v1.z; o[i][7] += a * v1.w;
            }
        }
    }

    // ---- epilogue: divide by l, write to [b][t][h][k]
    const int b = m >> 3, h = m & 7;
    #pragma unroll
    for (int i = 0; i < 4; i++) {
        const int t2 = q0 + rg * 4 + i;
        const float linv = 1.0f / l_sh[rg * 4 + i];
        float* dst = P + (((size_t)b * T_ + t2) * H_ + h) * KD_ + dg * 8;
        #pragma unroll
        for (int e = 0; e < 8; e++) dst[e] = o[i][e] * linv;
    }
}

// ---------------------------------------------------------------------------
extern "C" void kernel_launch(void* const* d_in, const int* in_sizes, int n_in,
                              void* d_out, int out_size)
{
    const float* x  = (const float*)d_in[0];
    const float* Wq = (const float*)d_in[1];
    const float* bq = (const float*)d_in[2];
    const float* Wk = (const float*)d_in[3];
    const float* bk = (const float*)d_in[4];
    const float* Wv = (const float*)d_in[5];
    const float* Wu = (const float*)d_in[6];
    const float* bu = (const float*)d_in[7];
    float* out = (float*)d_out;

    float *qp, *kp, *vp, *pp;
    cudaGetSymbolAddress((void**)&qp, g_Q);
    cudaGetSymbolAddress((void**)&kp, g_K);
    cudaGetSymbolAddress((void**)&vp, g_V);
    cudaGetSymbolAddress((void**)&pp, g_P);

    static bool attr_set = false;
    (void)attr_set;
    cudaFuncSetAttribute(attn_kernel, cudaFuncAttributeMaxDynamicSharedMemorySize,
                         ATTN_SMEM_FLOATS * (int)sizeof(float));

    const float qk_scale = 0.29730177875068026f;  // 1 / 128^0.25

    dim3 gq(T_ / 32, C_ / 128, B_);
    // Q conv: 5 taps, dil 2, pad 8, bias, remap, scale
    conv_gemm_kernel<5, 2, 8, 128, 8, C_, true, true><<<gq, 256>>>(x, Wq, bq, qp, qk_scale);
    // K conv
    conv_gemm_kernel<5, 2, 8, 128, 8, C_, true, true><<<gq, 256>>>(x, Wk, bk, kp, qk_scale);
    // V conv: 1 tap, no bias, remap, scale 1
    conv_gemm_kernel<1, 1, 0, 128, 32, C_, false, true><<<gq, 256>>>(x, Wv, nullptr, vp, 1.0f);

    // attention
    dim3 ga(T_ / 64, B_ * H_);
    attn_kernel<<<ga, 256, ATTN_SMEM_FLOATS * (int)sizeof(float)>>>(qp, kp, vp, pp);

    // output projection: plain GEMM 1024 -> 128, bias + silu
    dim3 gp(T_ / 32, 1, B_);
    conv_gemm_kernel<1, 1, 0, 1024, 32, 128, true, false><<<gp, 256>>>(pp, Wu, bu, out, 1.0f);
}

// round 3
// speedup vs baseline: 1.7620x; 1.7620x over previous
#include <cuda_runtime.h>
#include <cuda_fp16.h>
#include <cstdint>
#include <cstddef>

// Problem constants
#define B_ 4
#define T_ 2048
#define KD_ 128
#define H_ 8
#define C_ 1024   // KD_*H_

// Scratch (device globals; no allocation allowed)
__device__ __align__(256) __half g_Qh[(size_t)32 * T_ * KD_];   // [m][t'][d] flat view
__device__ __align__(256) __half g_Kh[(size_t)32 * T_ * KD_];   // [m][t'][d]
__device__ __align__(256) __half g_Vh[(size_t)32 * T_ * KD_];   // [m][t'][d]
__device__ __align__(256) float  g_P [(size_t)B_ * T_ * H_ * KD_];

__device__ __forceinline__ uint32_t smem_to_u32(const void* p) {
    uint32_t a;
    asm("{ .reg .u64 t; cvta.to.shared.u64 t, %1; cvt.u32.u64 %0, t; }" : "=r"(a) : "l"(p));
    return a;
}

#define LDMATRIX_X4(r0, r1, r2, r3, addr) \
    asm volatile("ldmatrix.sync.aligned.m8n8.x4.shared.b16 {%0,%1,%2,%3}, [%4];" \
        : "=r"(r0), "=r"(r1), "=r"(r2), "=r"(r3) : "r"(addr))
#define LDMATRIX_X4_T(r0, r1, r2, r3, addr) \
    asm volatile("ldmatrix.sync.aligned.m8n8.x4.trans.shared.b16 {%0,%1,%2,%3}, [%4];" \
        : "=r"(r0), "=r"(r1), "=r"(r2), "=r"(r3) : "r"(addr))
#define MMA_16816(c, a, b0v, b1v) \
    asm volatile("mma.sync.aligned.m16n8k16.row.col.f32.f16.f16.f32 " \
        "{%0,%1,%2,%3},{%4,%5,%6,%7},{%8,%9},{%0,%1,%2,%3};" \
        : "+f"((c)[0]), "+f"((c)[1]), "+f"((c)[2]), "+f"((c)[3]) \
        : "r"((a)[0]), "r"((a)[1]), "r"((a)[2]), "r"((a)[3]), "r"(b0v), "r"(b1v))

// ===========================================================================
// Conv-as-GEMM kernel (fp32 compute).
// OMODE: 0 = fp32 [b][t][c] (proj output). 1 = fp16 flat-view [m][t'][d]
// (== [b][t][h][k] linear; channel c = ko*8+h -> h=c&7, k=c>>3).
// ===========================================================================
template<int NTAPS, int DILT, int PADT, int CIN, int CI, int CTOT, bool BIAS, int OMODE, typename OutT>
__global__ void __launch_bounds__(256) conv_gemm_kernel(
    const float* __restrict__ X, const float* __restrict__ W,
    const float* __restrict__ bias, OutT* __restrict__ out, float scale)
{
    constexpr int TT = 32, TC = 128;
    constexpr int II = CI * NTAPS;
    constexpr int NROWS = TT + DILT * (NTAPS - 1);

    __shared__ float Xs[NROWS][CI + 1];
    __shared__ float Ws[II][TC];

    const int t0 = blockIdx.x * TT;
    const int c0 = blockIdx.y * TC;
    const int b  = blockIdx.z;
    const int tid = threadIdx.x;
    const int ct = tid & 31;
    const int tt = tid >> 5;

    float acc[4][4] = {};

    for (int cin0 = 0; cin0 < CIN; cin0 += CI) {
        __syncthreads();
        for (int idx = tid; idx < NROWS * CI; idx += 256) {
            int r  = idx / CI;
            int cc = idx - r * CI;
            int tg = t0 + r - PADT;
            float v = 0.0f;
            if (tg >= 0 && tg < T_)
                v = X[((size_t)b * T_ + tg) * CIN + cin0 + cc];
            Xs[r][cc] = v;
        }
        {
            int c = tid >> 1, half = tid & 1;
            const float* wp = W + ((size_t)(c0 + c) * CIN + cin0) * NTAPS + half * (II / 2);
            #pragma unroll
            for (int k2 = 0; k2 < II / 2; k2++)
                Ws[half * (II / 2) + k2][c] = wp[k2];
        }
        __syncthreads();

        #pragma unroll 2
        for (int cinl = 0; cinl < CI; cinl++) {
            #pragma unroll
            for (int j = 0; j < NTAPS; j++) {
                const int i = cinl * NTAPS + j;
                const int rb = tt * 4 + j * DILT;
                float a0 = Xs[rb + 0][cinl];
                float a1 = Xs[rb + 1][cinl];
                float a2 = Xs[rb + 2][cinl];
                float a3 = Xs[rb + 3][cinl];
                float4 bb = *(const float4*)&Ws[i][ct * 4];
                acc[0][0] += a0 * bb.x; acc[0][1] += a0 * bb.y; acc[0][2] += a0 * bb.z; acc[0][3] += a0 * bb.w;
                acc[1][0] += a1 * bb.x; acc[1][1] += a1 * bb.y; acc[1][2] += a1 * bb.z; acc[1][3] += a1 * bb.w;
                acc[2][0] += a2 * bb.x; acc[2][1] += a2 * bb.y; acc[2][2] += a2 * bb.z; acc[2][3] += a2 * bb.w;
                acc[3][0] += a3 * bb.x; acc[3][1] += a3 * bb.y; acc[3][2] += a3 * bb.z; acc[3][3] += a3 * bb.w;
            }
        }
    }

    #pragma unroll
    for (int cc = 0; cc < 4; cc++) {
        const int c = c0 + ct * 4 + cc;
        const float bv = BIAS ? bias[c] : 0.0f;
        #pragma unroll
        for (int tv = 0; tv < 4; tv++) {
            const int t = t0 + tt * 4 + tv;
            float y = acc[tv][cc] + bv;
            float s = y / (1.0f + __expf(-y));
            s *= scale;
            if (OMODE == 0) {
                ((float*)out)[((size_t)b * T_ + t) * CTOT + c] = s;
            } else {
                ((__half*)out)[(((size_t)b * T_ + t) * H_ + (c & 7)) * KD_ + (c >> 3)] = __float2half(s);
            }
        }
    }
}

// ===========================================================================
// Flash attention via mma.sync.m16n8k16 (fp16 in / fp32 accumulate).
// BM=128 (8 warps x 16 rows), BN=64, D=128. Unnormalized exp (logit std
// ~0.4), per-lane partial l, quad-reduce at end. Q in register A-frags.
// Smem: Q 32KB | K 16KB | V 16KB, all [row][d] with 16B-column XOR swizzle.
// ===========================================================================
#define BM 128
#define BN 64
#define OFF_K 32768
#define OFF_V 49152
#define ATTN_SMEM 65536

__global__ void __launch_bounds__(256, 1)
attn_mma_kernel(const __half* __restrict__ Qb, const __half* __restrict__ Kb,
                const __half* __restrict__ Vb, float* __restrict__ P)
{
    extern __shared__ char smc[];
    const uint32_t sQ = smem_to_u32(smc);
    const uint32_t sK = sQ + OFF_K;
    const uint32_t sV = sQ + OFF_V;

    const int tid = threadIdx.x, w = tid >> 5, l = tid & 31;
    const int m  = blockIdx.y;
    const int bi = (int)gridDim.x - 1 - (int)blockIdx.x;   // heavy tiles first
    const int q0 = bi * BM;
    const size_t mbase = (size_t)m * T_ * KD_;

    // ---- load Q tile [128 x 128] into swizzled smem
    {
        const uint4* src = (const uint4*)(Qb + mbase + (size_t)q0 * KD_);
        #pragma unroll
        for (int it = 0; it < 8; it++) {
            int idx = it * 256 + tid;
            int r = idx >> 4, cb = idx & 15;
            uint4 v = src[idx];
            *(uint4*)(smc + r * 256 + ((cb ^ (r & 7)) << 4)) = v;
        }
    }
    __syncthreads();

    // ---- extract Q A-frags: qa[kc][4], kc = k-chunk of 16
    uint32_t qa[8][4];
    {
        const int mi = l >> 3;
        const int rr = w * 16 + (mi & 1) * 8 + (l & 7);
        #pragma unroll
        for (int kc = 0; kc < 8; kc++) {
            const int cb = kc * 2 + (mi >> 1);
            uint32_t addr = sQ + rr * 256 + ((cb ^ (rr & 7)) << 4);
            LDMATRIX_X4(qa[kc][0], qa[kc][1], qa[kc][2], qa[kc][3], addr);
        }
    }

    float oacc[16][4] = {};
    float lsum0 = 0.0f, lsum1 = 0.0f;
    const int r0g = q0 + w * 16 + (l >> 2);  // global q row (lane's row 0)
    const int r1g = r0g + 8;

    const int ntiles = 2 * bi + 2;
    for (int kt = 0; kt < ntiles; kt++) {
        const int s0 = kt * BN;
        __syncthreads();
        // ---- load K and V tiles [64 x 128] swizzled
        {
            const uint4* ks = (const uint4*)(Kb + mbase + (size_t)s0 * KD_);
            const uint4* vs = (const uint4*)(Vb + mbase + (size_t)s0 * KD_);
            #pragma unroll
            for (int it = 0; it < 4; it++) {
                int idx = it * 256 + tid;
                int r = idx >> 4, cb = idx & 15;
                int off = r * 256 + ((cb ^ (r & 7)) << 4);
                *(uint4*)(smc + OFF_K + off) = ks[idx];
                *(uint4*)(smc + OFF_V + off) = vs[idx];
            }
        }
        __syncthreads();

        // ---- S = Q K^T : sacc[j] covers cols s0+8j..s0+8j+7
        float sacc[8][4] = {};
        {
            const int mi = l >> 3;
            #pragma unroll
            for (int kc = 0; kc < 8; kc++) {
                #pragma unroll
                for (int j = 0; j < 8; j += 2) {
                    const int nr = (j + (mi >> 1)) * 8 + (l & 7);
                    const int cb = kc * 2 + (mi & 1);
                    uint32_t addr = sK + nr * 256 + ((cb ^ (nr & 7)) << 4);
                    uint32_t b0, b1, b2, b3;
                    LDMATRIX_X4(b0, b1, b2, b3, addr);
                    MMA_16816(sacc[j],     qa[kc], b0, b1);
                    MMA_16816(sacc[j + 1], qa[kc], b2, b3);
                }
            }
        }

        // ---- mask + exp + pack into P A-frags
        uint32_t pa[4][4];
        {
            const int cb0 = s0 + 2 * (l & 3);
            #pragma unroll
            for (int j = 0; j < 8; j++) {
                const int c0 = cb0 + 8 * j, c1 = c0 + 1;
                float p00 = (c0 <= r0g) ? __expf(sacc[j][0]) : 0.0f;
                float p01 = (c1 <= r0g) ? __expf(sacc[j][1]) : 0.0f;
                float p10 = (c0 <= r1g) ? __expf(sacc[j][2]) : 0.0f;
                float p11 = (c1 <= r1g) ? __expf(sacc[j][3]) : 0.0f;
                lsum0 += p00 + p01;
                lsum1 += p10 + p11;
                __half2 ha = __floats2half2_rn(p00, p01);
                __half2 hb = __floats2half2_rn(p10, p11);
                const int kc2 = j >> 1, hi = (j & 1) * 2;
                pa[kc2][hi + 0] = *(uint32_t*)&ha;
                pa[kc2][hi + 1] = *(uint32_t*)&hb;
            }
        }

        // ---- O += P V : oacc[j] covers d = 8j..8j+7
        {
            const int mi = l >> 3;
            #pragma unroll
            for (int kc2 = 0; kc2 < 4; kc2++) {
                #pragma unroll
                for (int j = 0; j < 16; j += 2) {
                    const int sr = kc2 * 16 + (mi & 1) * 8 + (l & 7);
                    const int cb = j + (mi >> 1);
                    uint32_t addr = sV + sr * 256 + ((cb ^ (sr & 7)) << 4);
                    uint32_t b0, b1, b2, b3;
                    LDMATRIX_X4_T(b0, b1, b2, b3, addr);
                    MMA_16816(oacc[j],     pa[kc2], b0, b1);
                    MMA_16816(oacc[j + 1], pa[kc2], b2, b3);
                }
            }
        }
    }

    // ---- epilogue: reduce l over quad, divide, write [b][t][h][k] fp32
    lsum0 += __shfl_xor_sync(0xffffffffu, lsum0, 1);
    lsum0 += __shfl_xor_sync(0xffffffffu, lsum0, 2);
    lsum1 += __shfl_xor_sync(0xffffffffu, lsum1, 1);
    lsum1 += __shfl_xor_sync(0xffffffffu, lsum1, 2);
    const float li0 = 1.0f / lsum0, li1 = 1.0f / lsum1;

    const int b = m >> 3, h = m & 7;
    float* base0 = P + (((size_t)b * T_ + r0g) * H_ + h) * KD_ + 2 * (l & 3);
    float* base1 = P + (((size_t)b * T_ + r1g) * H_ + h) * KD_ + 2 * (l & 3);
    #pragma unroll
    for (int j = 0; j < 16; j++) {
        float2 v0 = make_float2(oacc[j][0] * li0, oacc[j][1] * li0);
        float2 v1 = make_float2(oacc[j][2] * li1, oacc[j][3] * li1);
        *(float2*)(base0 + 8 * j) = v0;
        *(float2*)(base1 + 8 * j) = v1;
    }
}

// ===========================================================================
extern "C" void kernel_launch(void* const* d_in, const int* in_sizes, int n_in,
                              void* d_out, int out_size)
{
    const float* x  = (const float*)d_in[0];
    const float* Wq = (const float*)d_in[1];
    const float* bq = (const float*)d_in[2];
    const float* Wk = (const float*)d_in[3];
    const float* bk = (const float*)d_in[4];
    const float* Wv = (const float*)d_in[5];
    const float* Wu = (const float*)d_in[6];
    const float* bu = (const float*)d_in[7];
    float* out = (float*)d_out;

    __half *qp, *kp, *vp;
    float* pp;
    cudaGetSymbolAddress((void**)&qp, g_Qh);
    cudaGetSymbolAddress((void**)&kp, g_Kh);
    cudaGetSymbolAddress((void**)&vp, g_Vh);
    cudaGetSymbolAddress((void**)&pp, g_P);

    cudaFuncSetAttribute(attn_mma_kernel, cudaFuncAttributeMaxDynamicSharedMemorySize, ATTN_SMEM);

    const float qk_scale = 0.29730177875068026f;  // 1 / 128^0.25

    dim3 gq(T_ / 32, C_ / 128, B_);
    conv_gemm_kernel<5, 2, 8, 128, 8, C_, true, 1, __half><<<gq, 256>>>(x, Wq, bq, qp, qk_scale);
    conv_gemm_kernel<5, 2, 8, 128, 8, C_, true, 1, __half><<<gq, 256>>>(x, Wk, bk, kp, qk_scale);
    conv_gemm_kernel<1, 1, 0, 128, 32, C_, false, 1, __half><<<gq, 256>>>(x, Wv, nullptr, vp, 1.0f);

    dim3 ga(T_ / BM, 32);
    attn_mma_kernel<<<ga, 256, ATTN_SMEM>>>(qp, kp, vp, pp);

    dim3 gp(T_ / 32, 1, B_);
    conv_gemm_kernel<1, 1, 0, 1024, 32, 128, true, 0, float><<<gp, 256>>>(pp, Wu, bu, out, 1.0f);
}

// round 4
// speedup vs baseline: 5.2747x; 2.9936x over previous
#include <cuda_runtime.h>
#include <cuda_fp16.h>
#include <cstdint>
#include <cstddef>

// Problem constants
#define B_ 4
#define T_ 2048
#define KD_ 128
#define H_ 8
#define C_ 1024   // KD_*H_

// Scratch (device globals; no allocation allowed)
__device__ __align__(256) __half g_xh [(size_t)B_ * T_ * KD_];    // x fp16 [b][t][cin]
__device__ __align__(256) __half g_Wq5[(size_t)5 * C_ * KD_];     // [tap][cout][cin]
__device__ __align__(256) __half g_Wk5[(size_t)5 * C_ * KD_];
__device__ __align__(256) __half g_Wv [(size_t)C_ * KD_];         // [cout][cin]
__device__ __align__(256) __half g_Wu [(size_t)KD_ * C_];         // [cout][f]
__device__ __align__(256) __half g_Qh [(size_t)32 * T_ * KD_];    // [m][t'][d] flat view
__device__ __align__(256) __half g_Kh [(size_t)32 * T_ * KD_];
__device__ __align__(256) __half g_Vh [(size_t)32 * T_ * KD_];
__device__ __align__(256) __half g_Ph [(size_t)B_ * T_ * C_];     // attn out [b][t][f]

__device__ __forceinline__ uint32_t smem_to_u32(const void* p) {
    uint32_t a;
    asm("{ .reg .u64 t; cvta.to.shared.u64 t, %1; cvt.u32.u64 %0, t; }" : "=r"(a) : "l"(p));
    return a;
}

#define LDMATRIX_X4(r0, r1, r2, r3, addr) \
    asm volatile("ldmatrix.sync.aligned.m8n8.x4.shared.b16 {%0,%1,%2,%3}, [%4];" \
        : "=r"(r0), "=r"(r1), "=r"(r2), "=r"(r3) : "r"(addr))
#define LDMATRIX_X4_T(r0, r1, r2, r3, addr) \
    asm volatile("ldmatrix.sync.aligned.m8n8.x4.trans.shared.b16 {%0,%1,%2,%3}, [%4];" \
        : "=r"(r0), "=r"(r1), "=r"(r2), "=r"(r3) : "r"(addr))
#define MMA_16816(c, a, b0v, b1v) \
    asm volatile("mma.sync.aligned.m16n8k16.row.col.f32.f16.f16.f32 " \
        "{%0,%1,%2,%3},{%4,%5,%6,%7},{%8,%9},{%0,%1,%2,%3};" \
        : "+f"((c)[0]), "+f"((c)[1]), "+f"((c)[2]), "+f"((c)[3]) \
        : "r"((a)[0]), "r"((a)[1]), "r"((a)[2]), "r"((a)[3]), "r"(b0v), "r"(b1v))

__device__ __forceinline__ float silu_f(float y) { return y / (1.0f + __expf(-y)); }

// ===========================================================================
// Prepack kernels
// ===========================================================================
__global__ void cvt_f2h_kernel(const float* __restrict__ src, __half* __restrict__ dst, int n) {
    int i = blockIdx.x * 256 + threadIdx.x;
    if (i < n) dst[i] = __float2half(src[i]);
}
// W [c=1024][cin=128][5] -> Wt [j][c][cin] fp16
__global__ void pack_w5_kernel(const float* __restrict__ W, __half* __restrict__ Wt) {
    int idx = blockIdx.x * 256 + threadIdx.x;   // 5*131072
    int cin = idx & 127, c = (idx >> 7) & 1023, j = idx >> 17;
    Wt[idx] = __float2half(W[((c << 7) + cin) * 5 + j]);
}

// ===========================================================================
// Generic mma.sync GEMM / dilated-conv kernel.
// out[b][t][c] = act( bias[c] + sum_{j,cin} Bw[j][c][cin] * A[b][t + j*DILT - PADT][cin] )
// CTA tile 128 t-rows x 128 cout. 256 thr / 8 warps, warp = 16 rows x 128 cols.
// Smem: A tile 32KB swizzled + B tile 32KB swizzled (dynamic, 64KB).
// OMODE 1: fp16 store remapped to [b][t][h=c&7][k=c>>3]  (Q/K/V)
// OMODE 3: fp32 store [b][t][NOUT]                        (projection)
// ===========================================================================
template<int NTAPS, int DILT, int PADT, int CIN, int NOUT, bool BIAS, int OMODE>
__global__ void __launch_bounds__(256, 1) gemm16_kernel(
    const __half* __restrict__ A, const __half* __restrict__ Bw,
    const float* __restrict__ bias, void* __restrict__ out, float scale)
{
    extern __shared__ char smc[];
    const uint32_t sA = smem_to_u32(smc);
    const uint32_t sB = sA + 32768;

    const int t0 = blockIdx.x * 128;
    const int c0 = blockIdx.y * 128;
    const int b  = blockIdx.z;
    const int tid = threadIdx.x, w = tid >> 5, l = tid & 31;
    const int mi = l >> 3;

    float cacc[16][4] = {};

    #pragma unroll 1
    for (int j = 0; j < NTAPS; j++) {
        #pragma unroll 1
        for (int ch = 0; ch < CIN / 128; ch++) {
            __syncthreads();
            // ---- load A tile (shifted rows, guard boundaries)
            #pragma unroll
            for (int it = 0; it < 8; it++) {
                int idx = it * 256 + tid;
                int r = idx >> 4, cb = idx & 15;
                int tg = t0 + r + j * DILT - PADT;
                uint4 v = make_uint4(0u, 0u, 0u, 0u);
                if (tg >= 0 && tg < T_)
                    v = *(const uint4*)(A + ((size_t)b * T_ + tg) * CIN + ch * 128 + cb * 8);
                *(uint4*)(smc + r * 256 + ((cb ^ (r & 7)) << 4)) = v;
            }
            // ---- load B tile
            #pragma unroll
            for (int it = 0; it < 8; it++) {
                int idx = it * 256 + tid;
                int r = idx >> 4, cb = idx & 15;
                uint4 v = *(const uint4*)(Bw + ((size_t)j * NOUT + c0 + r) * CIN + ch * 128 + cb * 8);
                *(uint4*)(smc + 32768 + r * 256 + ((cb ^ (r & 7)) << 4)) = v;
            }
            __syncthreads();
            // ---- compute: 8 k-chunks of 16
            #pragma unroll
            for (int kc = 0; kc < 8; kc++) {
                uint32_t a4[4];
                const int rr = w * 16 + (mi & 1) * 8 + (l & 7);
                const int cba = kc * 2 + (mi >> 1);
                LDMATRIX_X4(a4[0], a4[1], a4[2], a4[3],
                            sA + rr * 256 + ((cba ^ (rr & 7)) << 4));
                #pragma unroll
                for (int jn = 0; jn < 16; jn += 2) {
                    const int nr = (jn + (mi >> 1)) * 8 + (l & 7);
                    const int cbb = kc * 2 + (mi & 1);
                    uint32_t b0, b1, b2, b3;
                    LDMATRIX_X4(b0, b1, b2, b3, sB + nr * 256 + ((cbb ^ (nr & 7)) << 4));
                    MMA_16816(cacc[jn],     a4, b0, b1);
                    MMA_16816(cacc[jn + 1], a4, b2, b3);
                }
            }
        }
    }

    // ---- epilogue: bias + silu + scale, store
    const int tr0 = t0 + w * 16 + (l >> 2);
    const int tr1 = tr0 + 8;
    #pragma unroll
    for (int jn = 0; jn < 16; jn++) {
        const int c = c0 + 8 * jn + 2 * (l & 3);
        const float bv0 = BIAS ? bias[c] : 0.0f;
        const float bv1 = BIAS ? bias[c + 1] : 0.0f;
        float s00 = silu_f(cacc[jn][0] + bv0) * scale;
        float s01 = silu_f(cacc[jn][1] + bv1) * scale;
        float s10 = silu_f(cacc[jn][2] + bv0) * scale;
        float s11 = silu_f(cacc[jn][3] + bv1) * scale;
        if (OMODE == 1) {
            __half* o = (__half*)out;
            o[(((size_t)b * T_ + tr0) * H_ + (c & 7)) * KD_ + (c >> 3)]             = __float2half(s00);
            o[(((size_t)b * T_ + tr0) * H_ + ((c + 1) & 7)) * KD_ + ((c + 1) >> 3)] = __float2half(s01);
            o[(((size_t)b * T_ + tr1) * H_ + (c & 7)) * KD_ + (c >> 3)]             = __float2half(s10);
            o[(((size_t)b * T_ + tr1) * H_ + ((c + 1) & 7)) * KD_ + ((c + 1) >> 3)] = __float2half(s11);
        } else {
            float* o = (float*)out;
            *(float2*)(o + ((size_t)b * T_ + tr0) * NOUT + c) = make_float2(s00, s01);
            *(float2*)(o + ((size_t)b * T_ + tr1) * NOUT + c) = make_float2(s10, s11);
        }
    }
}

// ===========================================================================
// Flash attention via mma.sync.m16n8k16 (fp16 in / fp32 accumulate).
// BM=128 (8 warps x 16 rows), BN=64, D=128. Unnormalized exp, per-lane l.
// Writes fp16 P to [b][t][f = h*128 + k] (projection-ready layout).
// ===========================================================================
#define BM 128
#define BN 64
#define OFF_K 32768
#define OFF_V 49152
#define ATTN_SMEM 65536

__global__ void __launch_bounds__(256, 1)
attn_mma_kernel(const __half* __restrict__ Qb, const __half* __restrict__ Kb,
                const __half* __restrict__ Vb, __half* __restrict__ Ph)
{
    extern __shared__ char smc[];
    const uint32_t sQ = smem_to_u32(smc);
    const uint32_t sK = sQ + OFF_K;
    const uint32_t sV = sQ + OFF_V;

    const int tid = threadIdx.x, w = tid >> 5, l = tid & 31;
    const int m  = blockIdx.y;
    const int bi = (int)gridDim.x - 1 - (int)blockIdx.x;   // heavy tiles first
    const int q0 = bi * BM;
    const size_t mbase = (size_t)m * T_ * KD_;

    // ---- load Q tile [128 x 128] into swizzled smem
    {
        const uint4* src = (const uint4*)(Qb + mbase + (size_t)q0 * KD_);
        #pragma unroll
        for (int it = 0; it < 8; it++) {
            int idx = it * 256 + tid;
            int r = idx >> 4, cb = idx & 15;
            uint4 v = src[idx];
            *(uint4*)(smc + r * 256 + ((cb ^ (r & 7)) << 4)) = v;
        }
    }
    __syncthreads();

    // ---- extract Q A-frags
    uint32_t qa[8][4];
    {
        const int mi = l >> 3;
        const int rr = w * 16 + (mi & 1) * 8 + (l & 7);
        #pragma unroll
        for (int kc = 0; kc < 8; kc++) {
            const int cb = kc * 2 + (mi >> 1);
            uint32_t addr = sQ + rr * 256 + ((cb ^ (rr & 7)) << 4);
            LDMATRIX_X4(qa[kc][0], qa[kc][1], qa[kc][2], qa[kc][3], addr);
        }
    }

    float oacc[16][4] = {};
    float lsum0 = 0.0f, lsum1 = 0.0f;
    const int r0g = q0 + w * 16 + (l >> 2);
    const int r1g = r0g + 8;

    const int ntiles = 2 * bi + 2;
    for (int kt = 0; kt < ntiles; kt++) {
        const int s0 = kt * BN;
        __syncthreads();
        {
            const uint4* ks = (const uint4*)(Kb + mbase + (size_t)s0 * KD_);
            const uint4* vs = (const uint4*)(Vb + mbase + (size_t)s0 * KD_);
            #pragma unroll
            for (int it = 0; it < 4; it++) {
                int idx = it * 256 + tid;
                int r = idx >> 4, cb = idx & 15;
                int off = r * 256 + ((cb ^ (r & 7)) << 4);
                *(uint4*)(smc + OFF_K + off) = ks[idx];
                *(uint4*)(smc + OFF_V + off) = vs[idx];
            }
        }
        __syncthreads();

        // ---- S = Q K^T
        float sacc[8][4] = {};
        {
            const int mi = l >> 3;
            #pragma unroll
            for (int kc = 0; kc < 8; kc++) {
                #pragma unroll
                for (int j = 0; j < 8; j += 2) {
                    const int nr = (j + (mi >> 1)) * 8 + (l & 7);
                    const int cb = kc * 2 + (mi & 1);
                    uint32_t addr = sK + nr * 256 + ((cb ^ (nr & 7)) << 4);
                    uint32_t b0, b1, b2, b3;
                    LDMATRIX_X4(b0, b1, b2, b3, addr);
                    MMA_16816(sacc[j],     qa[kc], b0, b1);
                    MMA_16816(sacc[j + 1], qa[kc], b2, b3);
                }
            }
        }

        // ---- mask + exp + pack into P A-frags
        uint32_t pa[4][4];
        {
            const int cb0 = s0 + 2 * (l & 3);
            #pragma unroll
            for (int j = 0; j < 8; j++) {
                const int c0 = cb0 + 8 * j, c1 = c0 + 1;
                float p00 = (c0 <= r0g) ? __expf(sacc[j][0]) : 0.0f;
                float p01 = (c1 <= r0g) ? __expf(sacc[j][1]) : 0.0f;
                float p10 = (c0 <= r1g) ? __expf(sacc[j][2]) : 0.0f;
                float p11 = (c1 <= r1g) ? __expf(sacc[j][3]) : 0.0f;
                lsum0 += p00 + p01;
                lsum1 += p10 + p11;
                __half2 ha = __floats2half2_rn(p00, p01);
                __half2 hb = __floats2half2_rn(p10, p11);
                const int kc2 = j >> 1, hi = (j & 1) * 2;
                pa[kc2][hi + 0] = *(uint32_t*)&ha;
                pa[kc2][hi + 1] = *(uint32_t*)&hb;
            }
        }

        // ---- O += P V
        {
            const int mi = l >> 3;
            #pragma unroll
            for (int kc2 = 0; kc2 < 4; kc2++) {
                #pragma unroll
                for (int j = 0; j < 16; j += 2) {
                    const int sr = kc2 * 16 + (mi & 1) * 8 + (l & 7);
                    const int cb = j + (mi >> 1);
                    uint32_t addr = sV + sr * 256 + ((cb ^ (sr & 7)) << 4);
                    uint32_t b0, b1, b2, b3;
                    LDMATRIX_X4_T(b0, b1, b2, b3, addr);
                    MMA_16816(oacc[j],     pa[kc2], b0, b1);
                    MMA_16816(oacc[j + 1], pa[kc2], b2, b3);
                }
            }
        }
    }

    // ---- epilogue: reduce l over quad, divide, write fp16 [b][t][h*128+k]
    lsum0 += __shfl_xor_sync(0xffffffffu, lsum0, 1);
    lsum0 += __shfl_xor_sync(0xffffffffu, lsum0, 2);
    lsum1 += __shfl_xor_sync(0xffffffffu, lsum1, 1);
    lsum1 += __shfl_xor_sync(0xffffffffu, lsum1, 2);
    const float li0 = 1.0f / lsum0, li1 = 1.0f / lsum1;

    const int b = m >> 3, h = m & 7;
    __half* base0 = Ph + ((size_t)b * T_ + r0g) * C_ + h * KD_ + 2 * (l & 3);
    __half* base1 = Ph + ((size_t)b * T_ + r1g) * C_ + h * KD_ + 2 * (l & 3);
    #pragma unroll
    for (int j = 0; j < 16; j++) {
        *(__half2*)(base0 + 8 * j) = __floats2half2_rn(oacc[j][0] * li0, oacc[j][1] * li0);
        *(__half2*)(base1 + 8 * j) = __floats2half2_rn(oacc[j][2] * li1, oacc[j][3] * li1);
    }
}

// ===========================================================================
extern "C" void kernel_launch(void* const* d_in, const int* in_sizes, int n_in,
                              void* d_out, int out_size)
{
    const float* x  = (const float*)d_in[0];
    const float* Wq = (const float*)d_in[1];
    const float* bq = (const float*)d_in[2];
    const float* Wk = (const float*)d_in[3];
    const float* bk = (const float*)d_in[4];
    const float* Wv = (const float*)d_in[5];
    const float* Wu = (const float*)d_in[6];
    const float* bu = (const float*)d_in[7];
    float* out = (float*)d_out;

    __half *xh, *wq5, *wk5, *wv, *wu, *qp, *kp, *vp, *ph;
    cudaGetSymbolAddress((void**)&xh,  g_xh);
    cudaGetSymbolAddress((void**)&wq5, g_Wq5);
    cudaGetSymbolAddress((void**)&wk5, g_Wk5);
    cudaGetSymbolAddress((void**)&wv,  g_Wv);
    cudaGetSymbolAddress((void**)&wu,  g_Wu);
    cudaGetSymbolAddress((void**)&qp,  g_Qh);
    cudaGetSymbolAddress((void**)&kp,  g_Kh);
    cudaGetSymbolAddress((void**)&vp,  g_Vh);
    cudaGetSymbolAddress((void**)&ph,  g_Ph);

    cudaFuncSetAttribute(attn_mma_kernel, cudaFuncAttributeMaxDynamicSharedMemorySize, ATTN_SMEM);
    cudaFuncSetAttribute((gemm16_kernel<5, 2, 8, 128, 1024, true, 1>),
                         cudaFuncAttributeMaxDynamicSharedMemorySize, 65536);
    cudaFuncSetAttribute((gemm16_kernel<1, 1, 0, 128, 1024, false, 1>),
                         cudaFuncAttributeMaxDynamicSharedMemorySize, 65536);
    cudaFuncSetAttribute((gemm16_kernel<1, 1, 0, 1024, 128, true, 3>),
                         cudaFuncAttributeMaxDynamicSharedMemorySize, 65536);

    const float qk_scale = 0.29730177875068026f;  // 1 / 128^0.25

    // ---- prepack
    cvt_f2h_kernel<<<(B_ * T_ * KD_) / 256, 256>>>(x, xh, B_ * T_ * KD_);
    pack_w5_kernel<<<(5 * C_ * KD_) / 256, 256>>>(Wq, wq5);
    pack_w5_kernel<<<(5 * C_ * KD_) / 256, 256>>>(Wk, wk5);
    cvt_f2h_kernel<<<(C_ * KD_) / 256, 256>>>(Wv, wv, C_ * KD_);
    cvt_f2h_kernel<<<(KD_ * C_) / 256, 256>>>(Wu, wu, KD_ * C_);

    // ---- conv GEMMs
    dim3 gq(T_ / 128, C_ / 128, B_);
    gemm16_kernel<5, 2, 8, 128, 1024, true, 1><<<gq, 256, 65536>>>(xh, wq5, bq, qp, qk_scale);
    gemm16_kernel<5, 2, 8, 128, 1024, true, 1><<<gq, 256, 65536>>>(xh, wk5, bk, kp, qk_scale);
    gemm16_kernel<1, 1, 0, 128, 1024, false, 1><<<gq, 256, 65536>>>(xh, wv, nullptr, vp, 1.0f);

    // ---- attention
    dim3 ga(T_ / BM, 32);
    attn_mma_kernel<<<ga, 256, ATTN_SMEM>>>(qp, kp, vp, ph);

    // ---- output projection
    dim3 gp(T_ / 128, 1, B_);
    gemm16_kernel<1, 1, 0, 1024, 128, true, 3><<<gp, 256, 65536>>>(ph, wu, bu, out, 1.0f);
}

// round 6
// speedup vs baseline: 6.2902x; 1.1925x over previous
#include <cuda_runtime.h>
#include <cuda_fp16.h>
#include <cstdint>
#include <cstddef>

// Problem constants
#define B_ 4
#define T_ 2048
#define KD_ 128
#define H_ 8
#define C_ 1024   // KD_*H_

// Scratch (device globals; no allocation allowed)
__device__ __align__(256) __half g_xh [(size_t)B_ * T_ * KD_];    // x fp16 [b][t][cin]
__device__ __align__(256) __half g_Wq5[(size_t)5 * C_ * KD_];     // [tap][cout][cin]
__device__ __align__(256) __half g_Wk5[(size_t)5 * C_ * KD_];
__device__ __align__(256) __half g_Wv [(size_t)C_ * KD_];         // [cout][cin]
__device__ __align__(256) __half g_Wu [(size_t)KD_ * C_];         // [cout][f]
__device__ __align__(256) __half g_Qh [(size_t)32 * T_ * KD_];    // [m][t'][d] flat view
__device__ __align__(256) __half g_Kh [(size_t)32 * T_ * KD_];
__device__ __align__(256) __half g_Vh [(size_t)32 * T_ * KD_];
__device__ __align__(256) __half g_Ph [(size_t)B_ * T_ * C_];     // attn out [b][t][f]

__device__ __forceinline__ uint32_t smem_to_u32(const void* p) {
    uint32_t a;
    asm("{ .reg .u64 t; cvta.to.shared.u64 t, %1; cvt.u32.u64 %0, t; }" : "=r"(a) : "l"(p));
    return a;
}

#define LDMATRIX_X4(r0, r1, r2, r3, addr) \
    asm volatile("ldmatrix.sync.aligned.m8n8.x4.shared.b16 {%0,%1,%2,%3}, [%4];" \
        : "=r"(r0), "=r"(r1), "=r"(r2), "=r"(r3) : "r"(addr))
#define LDMATRIX_X4_T(r0, r1, r2, r3, addr) \
    asm volatile("ldmatrix.sync.aligned.m8n8.x4.trans.shared.b16 {%0,%1,%2,%3}, [%4];" \
        : "=r"(r0), "=r"(r1), "=r"(r2), "=r"(r3) : "r"(addr))
#define MMA_16816(c, a, b0v, b1v) \
    asm volatile("mma.sync.aligned.m16n8k16.row.col.f32.f16.f16.f32 " \
        "{%0,%1,%2,%3},{%4,%5,%6,%7},{%8,%9},{%0,%1,%2,%3};" \
        : "+f"((c)[0]), "+f"((c)[1]), "+f"((c)[2]), "+f"((c)[3]) \
        : "r"((a)[0]), "r"((a)[1]), "r"((a)[2]), "r"((a)[3]), "r"(b0v), "r"(b1v))

#define CP_ASYNC16(dst, src) \
    asm volatile("cp.async.cg.shared.global [%0], [%1], 16;" :: "r"(dst), "l"(src))
#define CP_COMMIT() asm volatile("cp.async.commit_group;" ::: "memory")
#define CP_WAIT0()  asm volatile("cp.async.wait_group 0;" ::: "memory")
#define CP_WAIT1()  asm volatile("cp.async.wait_group 1;" ::: "memory")

__device__ __forceinline__ float silu_f(float y) { return y / (1.0f + __expf(-y)); }

// ===========================================================================
// Prepack kernels
// ===========================================================================
__global__ void cvt_f2h_kernel(const float* __restrict__ src, __half* __restrict__ dst, int n) {
    int i = blockIdx.x * 256 + threadIdx.x;
    if (i < n) dst[i] = __float2half(src[i]);
}
// W [c=1024][cin=128][5] -> Wt [j][c][cin] fp16
__global__ void pack_w5_kernel(const float* __restrict__ W, __half* __restrict__ Wt) {
    int idx = blockIdx.x * 256 + threadIdx.x;   // 5*131072
    int cin = idx & 127, c = (idx >> 7) & 1023, j = idx >> 17;
    Wt[idx] = __float2half(W[((c << 7) + cin) * 5 + j]);
}

// ===========================================================================
// Merged Q/K dilated-conv kernel (A-resident, B double-buffered cp.async).
// grid = (T/128, 16, B); blockIdx.y>>3 selects Q(0)/K(1), &7 = cout tile.
// Smem: A 136 rows x 256B = 34816 | B bufs 2 x 32768  -> 100352 bytes.
// ===========================================================================
#define QK_SMEM (34816 + 2 * 32768)

__global__ void __launch_bounds__(256, 1) qkconv_kernel(
    const __half* __restrict__ A,
    const __half* __restrict__ Wq5, const __half* __restrict__ Wk5,
    const float* __restrict__ bq, const float* __restrict__ bk,
    __half* __restrict__ Qo, __half* __restrict__ Ko, float scale)
{
    extern __shared__ char smc[];
    const uint32_t sA  = smem_to_u32(smc);
    const uint32_t sB0 = sA + 34816;

    const int t0 = blockIdx.x * 128;
    const int cm = blockIdx.y;
    const int mat = cm >> 3;
    const int c0 = (cm & 7) * 128;
    const int b  = blockIdx.z;
    const __half* Bw  = mat ? Wk5 : Wq5;
    const float* bias = mat ? bk : bq;
    __half* out       = mat ? Ko : Qo;

    const int tid = threadIdx.x, w = tid >> 5, l = tid & 31;
    const int mi = l >> 3;

    // ---- prefetch B tap 0 into buf 0
    #pragma unroll
    for (int it = 0; it < 8; it++) {
        int idx = it * 256 + tid;
        int r = idx >> 4, cb = idx & 15;
        CP_ASYNC16(sB0 + r * 256 + ((cb ^ (r & 7)) << 4),
                   Bw + ((size_t)(c0 + r)) * 128 + cb * 8);
    }
    CP_COMMIT();

    // ---- load A rows t0-8 .. t0+127 (136 rows), guarded
    #pragma unroll
    for (int it = 0; it < 9; it++) {
        int idx = it * 256 + tid;
        if (idx < 136 * 16) {
            int r = idx >> 4, cb = idx & 15;
            int tg = t0 + r - 8;
            uint4 v = make_uint4(0u, 0u, 0u, 0u);
            if (tg >= 0 && tg < T_)
                v = *(const uint4*)(A + ((size_t)b * T_ + tg) * 128 + cb * 8);
            *(uint4*)(smc + r * 256 + ((cb ^ (r & 7)) << 4)) = v;
        }
    }

    float cacc[16][4] = {};

    #pragma unroll 1
    for (int j = 0; j < 5; j++) {
        __syncthreads();   // prior compute done (protects buf (j+1)&1); A visible at j=0
        if (j + 1 < 5) {
            const uint32_t sBn = sB0 + ((j + 1) & 1) * 32768;
            #pragma unroll
            for (int it = 0; it < 8; it++) {
                int idx = it * 256 + tid;
                int r = idx >> 4, cb = idx & 15;
                CP_ASYNC16(sBn + r * 256 + ((cb ^ (r & 7)) << 4),
                           Bw + ((size_t)(j + 1) * C_ + c0 + r) * 128 + cb * 8);
            }
            CP_COMMIT();
            CP_WAIT1();
        } else {
            CP_WAIT0();
        }
        __syncthreads();

        const uint32_t sB = sB0 + (j & 1) * 32768;
        const int rowoff = 2 * j;   // smem A row = local out row + 2j
        #pragma unroll
        for (int kc = 0; kc < 8; kc++) {
            uint32_t a4[4];
            const int rr = w * 16 + (mi & 1) * 8 + (l & 7) + rowoff;
            const int cba = kc * 2 + (mi >> 1);
            LDMATRIX_X4(a4[0], a4[1], a4[2], a4[3],
                        sA + rr * 256 + ((cba ^ (rr & 7)) << 4));
            #pragma unroll
            for (int jn = 0; jn < 16; jn += 2) {
                const int nr = (jn + (mi >> 1)) * 8 + (l & 7);
                const int cbb = kc * 2 + (mi & 1);
                uint32_t b0, b1, b2, b3;
                LDMATRIX_X4(b0, b1, b2, b3, sB + nr * 256 + ((cbb ^ (nr & 7)) << 4));
                MMA_16816(cacc[jn],     a4, b0, b1);
                MMA_16816(cacc[jn + 1], a4, b2, b3);
            }
        }
    }

    // ---- epilogue: bias + silu + scale, remapped fp16 store [b][t][h][k]
    const int tr0 = t0 + w * 16 + (l >> 2);
    const int tr1 = tr0 + 8;
    #pragma unroll
    for (int jn = 0; jn < 16; jn++) {
        const int c = c0 + 8 * jn + 2 * (l & 3);
        const float bv0 = bias[c];
        const float bv1 = bias[c + 1];
        float s00 = silu_f(cacc[jn][0] + bv0) * scale;
        float s01 = silu_f(cacc[jn][1] + bv1) * scale;
        float s10 = silu_f(cacc[jn][2] + bv0) * scale;
        float s11 = silu_f(cacc[jn][3] + bv1) * scale;
        out[(((size_t)b * T_ + tr0) * H_ + (c & 7)) * KD_ + (c >> 3)]             = __float2half(s00);
        out[(((size_t)b * T_ + tr0) * H_ + ((c + 1) & 7)) * KD_ + ((c + 1) >> 3)] = __float2half(s01);
        out[(((size_t)b * T_ + tr1) * H_ + (c & 7)) * KD_ + (c >> 3)]             = __float2half(s10);
        out[(((size_t)b * T_ + tr1) * H_ + ((c + 1) & 7)) * KD_ + ((c + 1) >> 3)] = __float2half(s11);
    }
}

// ===========================================================================
// Generic mma.sync GEMM kernel (V conv, projection). Unchanged from R4.
// ===========================================================================
template<int NTAPS, int DILT, int PADT, int CIN, int NOUT, bool BIAS, int OMODE>
__global__ void __launch_bounds__(256, 1) gemm16_kernel(
    const __half* __restrict__ A, const __half* __restrict__ Bw,
    const float* __restrict__ bias, void* __restrict__ out, float scale)
{
    extern __shared__ char smc[];
    const uint32_t sA = smem_to_u32(smc);
    const uint32_t sB = sA + 32768;

    const int t0 = blockIdx.x * 128;
    const int c0 = blockIdx.y * 128;
    const int b  = blockIdx.z;
    const int tid = threadIdx.x, w = tid >> 5, l = tid & 31;
    const int mi = l >> 3;

    float cacc[16][4] = {};

    #pragma unroll 1
    for (int j = 0; j < NTAPS; j++) {
        #pragma unroll 1
        for (int ch = 0; ch < CIN / 128; ch++) {
            __syncthreads();
            #pragma unroll
            for (int it = 0; it < 8; it++) {
                int idx = it * 256 + tid;
                int r = idx >> 4, cb = idx & 15;
                int tg = t0 + r + j * DILT - PADT;
                uint4 v = make_uint4(0u, 0u, 0u, 0u);
                if (tg >= 0 && tg < T_)
                    v = *(const uint4*)(A + ((size_t)b * T_ + tg) * CIN + ch * 128 + cb * 8);
                *(uint4*)(smc + r * 256 + ((cb ^ (r & 7)) << 4)) = v;
            }
            #pragma unroll
            for (int it = 0; it < 8; it++) {
                int idx = it * 256 + tid;
                int r = idx >> 4, cb = idx & 15;
                uint4 v = *(const uint4*)(Bw + ((size_t)j * NOUT + c0 + r) * CIN + ch * 128 + cb * 8);
                *(uint4*)(smc + 32768 + r * 256 + ((cb ^ (r & 7)) << 4)) = v;
            }
            __syncthreads();
            #pragma unroll
            for (int kc = 0; kc < 8; kc++) {
                uint32_t a4[4];
                const int rr = w * 16 + (mi & 1) * 8 + (l & 7);
                const int cba = kc * 2 + (mi >> 1);
                LDMATRIX_X4(a4[0], a4[1], a4[2], a4[3],
                            sA + rr * 256 + ((cba ^ (rr & 7)) << 4));
                #pragma unroll
                for (int jn = 0; jn < 16; jn += 2) {
                    const int nr = (jn + (mi >> 1)) * 8 + (l & 7);
                    const int cbb = kc * 2 + (mi & 1);
                    uint32_t b0, b1, b2, b3;
                    LDMATRIX_X4(b0, b1, b2, b3, sB + nr * 256 + ((cbb ^ (nr & 7)) << 4));
                    MMA_16816(cacc[jn],     a4, b0, b1);
                    MMA_16816(cacc[jn + 1], a4, b2, b3);
                }
            }
        }
    }

    const int tr0 = t0 + w * 16 + (l >> 2);
    const int tr1 = tr0 + 8;
    #pragma unroll
    for (int jn = 0; jn < 16; jn++) {
        const int c = c0 + 8 * jn + 2 * (l & 3);
        const float bv0 = BIAS ? bias[c] : 0.0f;
        const float bv1 = BIAS ? bias[c + 1] : 0.0f;
        float s00 = silu_f(cacc[jn][0] + bv0) * scale;
        float s01 = silu_f(cacc[jn][1] + bv1) * scale;
        float s10 = silu_f(cacc[jn][2] + bv0) * scale;
        float s11 = silu_f(cacc[jn][3] + bv1) * scale;
        if (OMODE == 1) {
            __half* o = (__half*)out;
            o[(((size_t)b * T_ + tr0) * H_ + (c & 7)) * KD_ + (c >> 3)]             = __float2half(s00);
            o[(((size_t)b * T_ + tr0) * H_ + ((c + 1) & 7)) * KD_ + ((c + 1) >> 3)] = __float2half(s01);
            o[(((size_t)b * T_ + tr1) * H_ + (c & 7)) * KD_ + (c >> 3)]             = __float2half(s10);
            o[(((size_t)b * T_ + tr1) * H_ + ((c + 1) & 7)) * KD_ + ((c + 1) >> 3)] = __float2half(s11);
        } else {
            float* o = (float*)out;
            *(float2*)(o + ((size_t)b * T_ + tr0) * NOUT + c) = make_float2(s00, s01);
            *(float2*)(o + ((size_t)b * T_ + tr1) * NOUT + c) = make_float2(s10, s11);
        }
    }
}

// ===========================================================================
// Flash attention via mma.sync (fp16/fp32), K/V double-buffered cp.async.
// Smem: Q 32KB | buf0: K16+V16 | buf1: K16+V16  -> 98304 bytes.
// ===========================================================================
#define BM 128
#define BN 64
#define ATTN_SMEM 98304

__global__ void __launch_bounds__(256, 1)
attn_mma_kernel(const __half* __restrict__ Qb, const __half* __restrict__ Kb,
                const __half* __restrict__ Vb, __half* __restrict__ Ph)
{
    extern __shared__ char smc[];
    const uint32_t sQ = smem_to_u32(smc);

    const int tid = threadIdx.x, w = tid >> 5, l = tid & 31;
    const int m  = blockIdx.y;
    const int bi = (int)gridDim.x - 1 - (int)blockIdx.x;   // heavy tiles first
    const int q0 = bi * BM;
    const size_t mbase = (size_t)m * T_ * KD_;
    const int ntiles = 2 * bi + 2;

    // ---- prefetch K/V tile 0 into buf 0
    {
        const __half* ks = Kb + mbase;
        const __half* vs = Vb + mbase;
        #pragma unroll
        for (int it = 0; it < 4; it++) {
            int idx = it * 256 + tid;
            int r = idx >> 4, cb = idx & 15;
            int off = r * 256 + ((cb ^ (r & 7)) << 4);
            CP_ASYNC16(sQ + 32768 + off, ks + (size_t)r * KD_ + cb * 8);
            CP_ASYNC16(sQ + 49152 + off, vs + (size_t)r * KD_ + cb * 8);
        }
        CP_COMMIT();
    }

    // ---- load Q tile [128 x 128] into swizzled smem
    {
        const uint4* src = (const uint4*)(Qb + mbase + (size_t)q0 * KD_);
        #pragma unroll
        for (int it = 0; it < 8; it++) {
            int idx = it * 256 + tid;
            int r = idx >> 4, cb = idx & 15;
            uint4 v = src[idx];
            *(uint4*)(smc + r * 256 + ((cb ^ (r & 7)) << 4)) = v;
        }
    }
    __syncthreads();

    // ---- extract Q A-frags
    uint32_t qa[8][4];
    {
        const int mi = l >> 3;
        const int rr = w * 16 + (mi & 1) * 8 + (l & 7);
        #pragma unroll
        for (int kc = 0; kc < 8; kc++) {
            const int cb = kc * 2 + (mi >> 1);
            LDMATRIX_X4(qa[kc][0], qa[kc][1], qa[kc][2], qa[kc][3],
                        sQ + rr * 256 + ((cb ^ (rr & 7)) << 4));
        }
    }

    float oacc[16][4] = {};
    float lsum0 = 0.0f, lsum1 = 0.0f;
    const int r0g = q0 + w * 16 + (l >> 2);
    const int r1g = r0g + 8;

    for (int kt = 0; kt < ntiles; kt++) {
        __syncthreads();   // prior compute done (protects buf (kt+1)&1)
        if (kt + 1 < ntiles) {
            const int s1 = (kt + 1) * BN;
            const uint32_t base = sQ + 32768 + ((kt + 1) & 1) * 32768;
            const __half* ks = Kb + mbase + (size_t)s1 * KD_;
            const __half* vs = Vb + mbase + (size_t)s1 * KD_;
            #pragma unroll
            for (int it = 0; it < 4; it++) {
                int idx = it * 256 + tid;
                int r = idx >> 4, cb = idx & 15;
                int off = r * 256 + ((cb ^ (r & 7)) << 4);
                CP_ASYNC16(base + off,         ks + (size_t)r * KD_ + cb * 8);
                CP_ASYNC16(base + 16384 + off, vs + (size_t)r * KD_ + cb * 8);
            }
            CP_COMMIT();
            CP_WAIT1();
        } else {
            CP_WAIT0();
        }
        __syncthreads();

        const uint32_t sK = sQ + 32768 + (kt & 1) * 32768;
        const uint32_t sV = sK + 16384;
        const int s0 = kt * BN;

        // ---- S = Q K^T
        float sacc[8][4] = {};
        {
            const int mi = l >> 3;
            #pragma unroll
            for (int kc = 0; kc < 8; kc++) {
                #pragma unroll
                for (int j = 0; j < 8; j += 2) {
                    const int nr = (j + (mi >> 1)) * 8 + (l & 7);
                    const int cb = kc * 2 + (mi & 1);
                    uint32_t b0, b1, b2, b3;
                    LDMATRIX_X4(b0, b1, b2, b3, sK + nr * 256 + ((cb ^ (nr & 7)) << 4));
                    MMA_16816(sacc[j],     qa[kc], b0, b1);
                    MMA_16816(sacc[j + 1], qa[kc], b2, b3);
                }
            }
        }

        // ---- mask + exp + pack into P A-frags
        uint32_t pa[4][4];
        {
            const int cb0 = s0 + 2 * (l & 3);
            #pragma unroll
            for (int j = 0; j < 8; j++) {
                const int c0 = cb0 + 8 * j, c1 = c0 + 1;
                float p00 = (c0 <= r0g) ? __expf(sacc[j][0]) : 0.0f;
                float p01 = (c1 <= r0g) ? __expf(sacc[j][1]) : 0.0f;
                float p10 = (c0 <= r1g) ? __expf(sacc[j][2]) : 0.0f;
                float p11 = (c1 <= r1g) ? __expf(sacc[j][3]) : 0.0f;
                lsum0 += p00 + p01;
                lsum1 += p10 + p11;
                __half2 ha = __floats2half2_rn(p00, p01);
                __half2 hb = __floats2half2_rn(p10, p11);
                const int kc2 = j >> 1, hi = (j & 1) * 2;
                pa[kc2][hi + 0] = *(uint32_t*)&ha;
                pa[kc2][hi + 1] = *(uint32_t*)&hb;
            }
        }

        // ---- O += P V
        {
            const int mi = l >> 3;
            #pragma unroll
            for (int kc2 = 0; kc2 < 4; kc2++) {
                #pragma unroll
                for (int j = 0; j < 16; j += 2) {
                    const int sr = kc2 * 16 + (mi & 1) * 8 + (l & 7);
                    const int cb = j + (mi >> 1);
                    uint32_t b0, b1, b2, b3;
                    LDMATRIX_X4_T(b0, b1, b2, b3, sV + sr * 256 + ((cb ^ (sr & 7)) << 4));
                    MMA_16816(oacc[j],     pa[kc2], b0, b1);
                    MMA_16816(oacc[j + 1], pa[kc2], b2, b3);
                }
            }
        }
    }

    // ---- epilogue
    lsum0 += __shfl_xor_sync(0xffffffffu, lsum0, 1);
    lsum0 += __shfl_xor_sync(0xffffffffu, lsum0, 2);
    lsum1 += __shfl_xor_sync(0xffffffffu, lsum1, 1);
    lsum1 += __shfl_xor_sync(0xffffffffu, lsum1, 2);
    const float li0 = 1.0f / lsum0, li1 = 1.0f / lsum1;

    const int b = m >> 3, h = m & 7;
    __half* base0 = Ph + ((size_t)b * T_ + r0g) * C_ + h * KD_ + 2 * (l & 3);
    __half* base1 = Ph + ((size_t)b * T_ + r1g) * C_ + h * KD_ + 2 * (l & 3);
    #pragma unroll
    for (int j = 0; j < 16; j++) {
        *(__half2*)(base0 + 8 * j) = __floats2half2_rn(oacc[j][0] * li0, oacc[j][1] * li0);
        *(__half2*)(base1 + 8 * j) = __floats2half2_rn(oacc[j][2] * li1, oacc[j][3] * li1);
    }
}

// ===========================================================================
extern "C" void kernel_launch(void* const* d_in, const int* in_sizes, int n_in,
                              void* d_out, int out_size)
{
    const float* x  = (const float*)d_in[0];
    const float* Wq = (const float*)d_in[1];
    const float* bq = (const float*)d_in[2];
    const float* Wk = (const float*)d_in[3];
    const float* bk = (const float*)d_in[4];
    const float* Wv = (const float*)d_in[5];
    const float* Wu = (const float*)d_in[6];
    const float* bu = (const float*)d_in[7];
    float* out = (float*)d_out;

    __half *xh, *wq5, *wk5, *wv, *wu, *qp, *kp, *vp, *ph;
    cudaGetSymbolAddress((void**)&xh,  g_xh);
    cudaGetSymbolAddress((void**)&wq5, g_Wq5);
    cudaGetSymbolAddress((void**)&wk5, g_Wk5);
    cudaGetSymbolAddress((void**)&wv,  g_Wv);
    cudaGetSymbolAddress((void**)&wu,  g_Wu);
    cudaGetSymbolAddress((void**)&qp,  g_Qh);
    cudaGetSymbolAddress((void**)&kp,  g_Kh);
    cudaGetSymbolAddress((void**)&vp,  g_Vh);
    cudaGetSymbolAddress((void**)&ph,  g_Ph);

    cudaFuncSetAttribute(attn_mma_kernel, cudaFuncAttributeMaxDynamicSharedMemorySize, ATTN_SMEM);
    cudaFuncSetAttribute(qkconv_kernel, cudaFuncAttributeMaxDynamicSharedMemorySize, QK_SMEM);
    cudaFuncSetAttribute((gemm16_kernel<1, 1, 0, 128, 1024, false, 1>),
                         cudaFuncAttributeMaxDynamicSharedMemorySize, 65536);
    cudaFuncSetAttribute((gemm16_kernel<1, 1, 0, 1024, 128, true, 3>),
                         cudaFuncAttributeMaxDynamicSharedMemorySize, 65536);

    const float qk_scale = 0.29730177875068026f;  // 1 / 128^0.25

    // ---- prepack
    cvt_f2h_kernel<<<(B_ * T_ * KD_) / 256, 256>>>(x, xh, B_ * T_ * KD_);
    pack_w5_kernel<<<(5 * C_ * KD_) / 256, 256>>>(Wq, wq5);
    pack_w5_kernel<<<(5 * C_ * KD_) / 256, 256>>>(Wk, wk5);
    cvt_f2h_kernel<<<(C_ * KD_) / 256, 256>>>(Wv, wv, C_ * KD_);
    cvt_f2h_kernel<<<(KD_ * C_) / 256, 256>>>(Wu, wu, KD_ * C_);

    // ---- Q+K conv (merged), V conv
    dim3 gqk(T_ / 128, 16, B_);
    qkconv_kernel<<<gqk, 256, QK_SMEM>>>(xh, wq5, wk5, bq, bk, qp, kp, qk_scale);
    dim3 gv(T_ / 128, C_ / 128, B_);
    gemm16_kernel<1, 1, 0, 128, 1024, false, 1><<<gv, 256, 65536>>>(xh, wv, nullptr, vp, 1.0f);

    // ---- attention
    dim3 ga(T_ / BM, 32);
    attn_mma_kernel<<<ga, 256, ATTN_SMEM>>>(qp, kp, vp, ph);

    // ---- output projection
    dim3 gp(T_ / 128, 1, B_);
    gemm16_kernel<1, 1, 0, 1024, 128, true, 3><<<gp, 256, 65536>>>(ph, wu, bu, out, 1.0f);
}

// round 8
// speedup vs baseline: 6.7931x; 1.0800x over previous
#include <cuda_runtime.h>
#include <cuda_fp16.h>
#include <cstdint>
#include <cstddef>

// Problem constants
#define B_ 4
#define T_ 2048
#define KD_ 128
#define H_ 8
#define C_ 1024   // KD_*H_
#define PSPLIT 4

// Scratch (device globals; no allocation allowed)
__device__ __align__(256) __half g_xh [(size_t)B_ * T_ * KD_];    // x fp16 [b][t][cin]
__device__ __align__(256) __half g_Wq5[(size_t)5 * C_ * KD_];     // [tap][cout][cin]
__device__ __align__(256) __half g_Wk5[(size_t)5 * C_ * KD_];
__device__ __align__(256) __half g_Wv [(size_t)C_ * KD_];         // [cout][cin]
__device__ __align__(256) __half g_Wu [(size_t)KD_ * C_];         // [cout][f]
__device__ __align__(256) __half g_Qh [(size_t)32 * T_ * KD_];    // [m][t'][d] flat view
__device__ __align__(256) __half g_Kh [(size_t)32 * T_ * KD_];
__device__ __align__(256) __half g_Vh [(size_t)32 * T_ * KD_];
__device__ __align__(256) __half g_Ph [(size_t)B_ * T_ * C_];     // attn out [b][t][f]
__device__ __align__(256) float  g_acc[(size_t)PSPLIT * B_ * T_ * KD_];  // proj partials

__device__ __forceinline__ uint32_t smem_to_u32(const void* p) {
    uint32_t a;
    asm("{ .reg .u64 t; cvta.to.shared.u64 t, %1; cvt.u32.u64 %0, t; }" : "=r"(a) : "l"(p));
    return a;
}

#define LDMATRIX_X4(r0, r1, r2, r3, addr) \
    asm volatile("ldmatrix.sync.aligned.m8n8.x4.shared.b16 {%0,%1,%2,%3}, [%4];" \
        : "=r"(r0), "=r"(r1), "=r"(r2), "=r"(r3) : "r"(addr))
#define LDMATRIX_X4_T(r0, r1, r2, r3, addr) \
    asm volatile("ldmatrix.sync.aligned.m8n8.x4.trans.shared.b16 {%0,%1,%2,%3}, [%4];" \
        : "=r"(r0), "=r"(r1), "=r"(r2), "=r"(r3) : "r"(addr))
#define MMA_16816(c, a, b0v, b1v) \
    asm volatile("mma.sync.aligned.m16n8k16.row.col.f32.f16.f16.f32 " \
        "{%0,%1,%2,%3},{%4,%5,%6,%7},{%8,%9},{%0,%1,%2,%3};" \
        : "+f"((c)[0]), "+f"((c)[1]), "+f"((c)[2]), "+f"((c)[3]) \
        : "r"((a)[0]), "r"((a)[1]), "r"((a)[2]), "r"((a)[3]), "r"(b0v), "r"(b1v))

#define CP_ASYNC16(dst, src) \
    asm volatile("cp.async.cg.shared.global [%0], [%1], 16;" :: "r"(dst), "l"(src))
#define CP_COMMIT() asm volatile("cp.async.commit_group;" ::: "memory")
template<int N> __device__ __forceinline__ void cp_wait() {
    asm volatile("cp.async.wait_group %0;" :: "n"(N) : "memory");
}
__device__ __forceinline__ void cp_wait_rt(int n) {
    switch (n) {
        case 0: cp_wait<0>(); break;
        case 1: cp_wait<1>(); break;
        case 2: cp_wait<2>(); break;
        case 3: cp_wait<3>(); break;
        default: cp_wait<4>(); break;
    }
}

__device__ __forceinline__ float silu_f(float y) { return y / (1.0f + __expf(-y)); }

// ===========================================================================
// Fused prepack: x->fp16, Wq/Wk tap-major fp16, Wv/Wu fp16.
// ===========================================================================
#define N_X  (B_ * T_ * KD_)        // 1048576
#define N_W5 (5 * C_ * KD_)         // 655360
#define N_WV (C_ * KD_)             // 131072
#define N_WU (KD_ * C_)             // 131072
#define N_PACK (N_X + 2 * N_W5 + N_WV + N_WU)

__global__ void pack_all_kernel(
    const float* __restrict__ x, const float* __restrict__ Wq,
    const float* __restrict__ Wk, const float* __restrict__ Wv,
    const float* __restrict__ Wu,
    __half* __restrict__ xh, __half* __restrict__ wq5, __half* __restrict__ wk5,
    __half* __restrict__ wv, __half* __restrict__ wu)
{
    int i = blockIdx.x * 256 + threadIdx.x;
    if (i < N_X) { xh[i] = __float2half(x[i]); return; }
    i -= N_X;
    if (i < N_W5) {
        int cin = i & 127, c = (i >> 7) & 1023, j = i >> 17;
        wq5[i] = __float2half(Wq[((c << 7) + cin) * 5 + j]);
        return;
    }
    i -= N_W5;
    if (i < N_W5) {
        int cin = i & 127, c = (i >> 7) & 1023, j = i >> 17;
        wk5[i] = __float2half(Wk[((c << 7) + cin) * 5 + j]);
        return;
    }
    i -= N_W5;
    if (i < N_WV) { wv[i] = __float2half(Wv[i]); return; }
    i -= N_WV;
    if (i < N_WU) { wu[i] = __float2half(Wu[i]); }
}

// ===========================================================================
// Merged Q/K dilated-conv kernel. A-resident; ALL 5 weight tap buffers
// prefetched via cp.async at CTA start (deep pipeline, 1 sync per tap).
// Smem: A 136 rows x 256B = 34816 | 5 x 32768 B bufs -> 198656 bytes.
// ===========================================================================
#define QK_SMEM (34816 + 5 * 32768)

__global__ void __launch_bounds__(256, 1) qkconv_kernel(
    const __half* __restrict__ A,
    const __half* __restrict__ Wq5, const __half* __restrict__ Wk5,
    const float* __restrict__ bq, const float* __restrict__ bk,
    __half* __restrict__ Qo, __half* __restrict__ Ko, float scale)
{
    extern __shared__ char smc[];
    const uint32_t sA  = smem_to_u32(smc);
    const uint32_t sB0 = sA + 34816;

    const int t0 = blockIdx.x * 128;
    const int cm = blockIdx.y;
    const int mat = cm >> 3;
    const int c0 = (cm & 7) * 128;
    const int b  = blockIdx.z;
    const __half* Bw  = mat ? Wk5 : Wq5;
    const float* bias = mat ? bk : bq;
    __half* out       = mat ? Ko : Qo;

    const int tid = threadIdx.x, w = tid >> 5, l = tid & 31;
    const int mi = l >> 3;

    // ---- prefetch ALL 5 tap weight tiles (5 commit groups)
    #pragma unroll
    for (int j = 0; j < 5; j++) {
        #pragma unroll
        for (int it = 0; it < 8; it++) {
            int idx = it * 256 + tid;
            int r = idx >> 4, cb = idx & 15;
            CP_ASYNC16(sB0 + j * 32768 + r * 256 + ((cb ^ (r & 7)) << 4),
                       Bw + ((size_t)j * C_ + c0 + r) * 128 + cb * 8);
        }
        CP_COMMIT();
    }

    // ---- load A rows t0-8 .. t0+127 (136 rows), guarded
    #pragma unroll
    for (int it = 0; it < 9; it++) {
        int idx = it * 256 + tid;
        if (idx < 136 * 16) {
            int r = idx >> 4, cb = idx & 15;
            int tg = t0 + r - 8;
            uint4 v = make_uint4(0u, 0u, 0u, 0u);
            if (tg >= 0 && tg < T_)
                v = *(const uint4*)(A + ((size_t)b * T_ + tg) * 128 + cb * 8);
            *(uint4*)(smc + r * 256 + ((cb ^ (r & 7)) << 4)) = v;
        }
    }

    float cacc[16][4] = {};

    #pragma unroll
    for (int j = 0; j < 5; j++) {
        cp_wait_rt(4 - j);   // groups 0..j complete (constant after unroll)
        __syncthreads();     // cross-thread visibility (A too, at j=0)

        const uint32_t sB = sB0 + j * 32768;
        const int rowoff = 2 * j;   // smem A row = local out row + 2j
        #pragma unroll
        for (int kc = 0; kc < 8; kc++) {
            uint32_t a4[4];
            const int rr = w * 16 + (mi & 1) * 8 + (l & 7) + rowoff;
            const int cba = kc * 2 + (mi >> 1);
            LDMATRIX_X4(a4[0], a4[1], a4[2], a4[3],
                        sA + rr * 256 + ((cba ^ (rr & 7)) << 4));
            #pragma unroll
            for (int jn = 0; jn < 16; jn += 2) {
                const int nr = (jn + (mi >> 1)) * 8 + (l & 7);
                const int cbb = kc * 2 + (mi & 1);
                uint32_t b0, b1, b2, b3;
                LDMATRIX_X4(b0, b1, b2, b3, sB + nr * 256 + ((cbb ^ (nr & 7)) << 4));
                MMA_16816(cacc[jn],     a4, b0, b1);
                MMA_16816(cacc[jn + 1], a4, b2, b3);
            }
        }
    }

    // ---- epilogue: bias + silu + scale, remapped fp16 store [b][t][h][k]
    const int tr0 = t0 + w * 16 + (l >> 2);
    const int tr1 = tr0 + 8;
    #pragma unroll
    for (int jn = 0; jn < 16; jn++) {
        const int c = c0 + 8 * jn + 2 * (l & 3);
        const float bv0 = bias[c];
        const float bv1 = bias[c + 1];
        float s00 = silu_f(cacc[jn][0] + bv0) * scale;
        float s01 = silu_f(cacc[jn][1] + bv1) * scale;
        float s10 = silu_f(cacc[jn][2] + bv0) * scale;
        float s11 = silu_f(cacc[jn][3] + bv1) * scale;
        out[(((size_t)b * T_ + tr0) * H_ + (c & 7)) * KD_ + (c >> 3)]             = __float2half(s00);
        out[(((size_t)b * T_ + tr0) * H_ + ((c + 1) & 7)) * KD_ + ((c + 1) >> 3)] = __float2half(s01);
        out[(((size_t)b * T_ + tr1) * H_ + (c & 7)) * KD_ + (c >> 3)]             = __float2half(s10);
        out[(((size_t)b * T_ + tr1) * H_ + ((c + 1) & 7)) * KD_ + ((c + 1) >> 3)] = __float2half(s11);
    }
}

// ===========================================================================
// Generic mma.sync GEMM kernel (V conv).
// ===========================================================================
template<int NTAPS, int DILT, int PADT, int CIN, int NOUT, bool BIAS, int OMODE>
__global__ void __launch_bounds__(256, 1) gemm16_kernel(
    const __half* __restrict__ A, const __half* __restrict__ Bw,
    const float* __restrict__ bias, void* __restrict__ out, float scale)
{
    extern __shared__ char smc[];
    const uint32_t sA = smem_to_u32(smc);
    const uint32_t sB = sA + 32768;

    const int t0 = blockIdx.x * 128;
    const int c0 = blockIdx.y * 128;
    const int b  = blockIdx.z;
    const int tid = threadIdx.x, w = tid >> 5, l = tid & 31;
    const int mi = l >> 3;

    float cacc[16][4] = {};

    #pragma unroll 1
    for (int j = 0; j < NTAPS; j++) {
        #pragma unroll 1
        for (int ch = 0; ch < CIN / 128; ch++) {
            __syncthreads();
            #pragma unroll
            for (int it = 0; it < 8; it++) {
                int idx = it * 256 + tid;
                int r = idx >> 4, cb = idx & 15;
                int tg = t0 + r + j * DILT - PADT;
                uint4 v = make_uint4(0u, 0u, 0u, 0u);
                if (tg >= 0 && tg < T_)
                    v = *(const uint4*)(A + ((size_t)b * T_ + tg) * CIN + ch * 128 + cb * 8);
                *(uint4*)(smc + r * 256 + ((cb ^ (r & 7)) << 4)) = v;
            }
            #pragma unroll
            for (int it = 0; it < 8; it++) {
                int idx = it * 256 + tid;
                int r = idx >> 4, cb = idx & 15;
                uint4 v = *(const uint4*)(Bw + ((size_t)j * NOUT + c0 + r) * CIN + ch * 128 + cb * 8);
                *(uint4*)(smc + 32768 + r * 256 + ((cb ^ (r & 7)) << 4)) = v;
            }
            __syncthreads();
            #pragma unroll
            for (int kc = 0; kc < 8; kc++) {
                uint32_t a4[4];
                const int rr = w * 16 + (mi & 1) * 8 + (l & 7);
                const int cba = kc * 2 + (mi >> 1);
                LDMATRIX_X4(a4[0], a4[1], a4[2], a4[3],
                            sA + rr * 256 + ((cba ^ (rr & 7)) << 4));
                #pragma unroll
                for (int jn = 0; jn < 16; jn += 2) {
                    const int nr = (jn + (mi >> 1)) * 8 + (l & 7);
                    const int cbb = kc * 2 + (mi & 1);
                    uint32_t b0, b1, b2, b3;
                    LDMATRIX_X4(b0, b1, b2, b3, sB + nr * 256 + ((cbb ^ (nr & 7)) << 4));
                    MMA_16816(cacc[jn],     a4, b0, b1);
                    MMA_16816(cacc[jn + 1], a4, b2, b3);
                }
            }
        }
    }

    const int tr0 = t0 + w * 16 + (l >> 2);
    const int tr1 = tr0 + 8;
    #pragma unroll
    for (int jn = 0; jn < 16; jn++) {
        const int c = c0 + 8 * jn + 2 * (l & 3);
        const float bv0 = BIAS ? bias[c] : 0.0f;
        const float bv1 = BIAS ? bias[c + 1] : 0.0f;
        float s00 = silu_f(cacc[jn][0] + bv0) * scale;
        float s01 = silu_f(cacc[jn][1] + bv1) * scale;
        float s10 = silu_f(cacc[jn][2] + bv0) * scale;
        float s11 = silu_f(cacc[jn][3] + bv1) * scale;
        if (OMODE == 1) {
            __half* o = (__half*)out;
            o[(((size_t)b * T_ + tr0) * H_ + (c & 7)) * KD_ + (c >> 3)]             = __float2half(s00);
            o[(((size_t)b * T_ + tr0) * H_ + ((c + 1) & 7)) * KD_ + ((c + 1) >> 3)] = __float2half(s01);
            o[(((size_t)b * T_ + tr1) * H_ + (c & 7)) * KD_ + (c >> 3)]             = __float2half(s10);
            o[(((size_t)b * T_ + tr1) * H_ + ((c + 1) & 7)) * KD_ + ((c + 1) >> 3)] = __float2half(s11);
        } else {
            float* o = (float*)out;
            *(float2*)(o + ((size_t)b * T_ + tr0) * NOUT + c) = make_float2(s00, s01);
            *(float2*)(o + ((size_t)b * T_ + tr1) * NOUT + c) = make_float2(s10, s11);
        }
    }
}

// ===========================================================================
// Projection with split-K: partial GEMM (no act) + reduce(bias+silu).
// Partial: grid (T/128, PSPLIT, B). Split s covers f in [s*256, s*256+256).
// ===========================================================================
__global__ void __launch_bounds__(256, 1) proj_partial_kernel(
    const __half* __restrict__ A, const __half* __restrict__ Bw,
    float* __restrict__ part)
{
    extern __shared__ char smc[];
    const uint32_t sA = smem_to_u32(smc);
    const uint32_t sB = sA + 32768;

    const int t0 = blockIdx.x * 128;
    const int sp = blockIdx.y;
    const int b  = blockIdx.z;
    const int tid = threadIdx.x, w = tid >> 5, l = tid & 31;
    const int mi = l >> 3;

    float cacc[16][4] = {};

    #pragma unroll 1
    for (int ch = 0; ch < 2; ch++) {
        const int cin0 = sp * 256 + ch * 128;
        __syncthreads();
        #pragma unroll
        for (int it = 0; it < 8; it++) {
            int idx = it * 256 + tid;
            int r = idx >> 4, cb = idx & 15;
            uint4 v = *(const uint4*)(A + ((size_t)b * T_ + t0 + r) * C_ + cin0 + cb * 8);
            *(uint4*)(smc + r * 256 + ((cb ^ (r & 7)) << 4)) = v;
        }
        #pragma unroll
        for (int it = 0; it < 8; it++) {
            int idx = it * 256 + tid;
            int r = idx >> 4, cb = idx & 15;
            uint4 v = *(const uint4*)(Bw + (size_t)r * C_ + cin0 + cb * 8);
            *(uint4*)(smc + 32768 + r * 256 + ((cb ^ (r & 7)) << 4)) = v;
        }
        __syncthreads();
        #pragma unroll
        for (int kc = 0; kc < 8; kc++) {
            uint32_t a4[4];
            const int rr = w * 16 + (mi & 1) * 8 + (l & 7);
            const int cba = kc * 2 + (mi >> 1);
            LDMATRIX_X4(a4[0], a4[1], a4[2], a4[3],
                        sA + rr * 256 + ((cba ^ (rr & 7)) << 4));
            #pragma unroll
            for (int jn = 0; jn < 16; jn += 2) {
                const int nr = (jn + (mi >> 1)) * 8 + (l & 7);
                const int cbb = kc * 2 + (mi & 1);
                uint32_t b0, b1, b2, b3;
                LDMATRIX_X4(b0, b1, b2, b3, sB + nr * 256 + ((cbb ^ (nr & 7)) << 4));
                MMA_16816(cacc[jn],     a4, b0, b1);
                MMA_16816(cacc[jn + 1], a4, b2, b3);
            }
        }
    }

    const int tr0 = t0 + w * 16 + (l >> 2);
    const int tr1 = tr0 + 8;
    float* dst = part + (size_t)sp * (B_ * T_ * KD_);
    #pragma unroll
    for (int jn = 0; jn < 16; jn++) {
        const int c = 8 * jn + 2 * (l & 3);
        *(float2*)(dst + ((size_t)b * T_ + tr0) * KD_ + c) = make_float2(cacc[jn][0], cacc[jn][1]);
        *(float2*)(dst + ((size_t)b * T_ + tr1) * KD_ + c) = make_float2(cacc[jn][2], cacc[jn][3]);
    }
}

__global__ void proj_reduce_kernel(const float* __restrict__ part,
                                   const float* __restrict__ bu,
                                   float* __restrict__ out)
{
    const int i = blockIdx.x * 256 + threadIdx.x;   // over B*T*128
    const int c = i & 127;
    const int S = B_ * T_ * KD_;
    float s = part[i] + part[i + S] + part[i + 2 * S] + part[i + 3 * S];
    out[i] = silu_f(s + bu[c]);
}

// ===========================================================================
// Flash attention via mma.sync; K/V double-buffered cp.async.
// Q/K carry sqrt(log2e) factor -> S is in log2 domain; exp via ex2.f16x2.
// Grid: 1D 512, qi-major heavy-first for global load balance.
// ===========================================================================
#define BM 128
#define BN 64
#define ATTN_SMEM 98304

__global__ void __launch_bounds__(256, 1)
attn_mma_kernel(const __half* __restrict__ Qb, const __half* __restrict__ Kb,
                const __half* __restrict__ Vb, __half* __restrict__ Ph)
{
    extern __shared__ char smc[];
    const uint32_t sQ = smem_to_u32(smc);

    const int tid = threadIdx.x, w = tid >> 5, l = tid & 31;
    const int bid = blockIdx.x;
    const int bi  = 15 - (bid >> 5);       // q-tile index, heavy (15) first
    const int m   = bid & 31;
    const int q0  = bi * BM;
    const size_t mbase = (size_t)m * T_ * KD_;
    const int ntiles = 2 * bi + 2;

    // ---- prefetch K/V tile 0 into buf 0
    {
        const __half* ks = Kb + mbase;
        const __half* vs = Vb + mbase;
        #pragma unroll
        for (int it = 0; it < 4; it++) {
            int idx = it * 256 + tid;
            int r = idx >> 4, cb = idx & 15;
            int off = r * 256 + ((cb ^ (r & 7)) << 4);
            CP_ASYNC16(sQ + 32768 + off, ks + (size_t)r * KD_ + cb * 8);
            CP_ASYNC16(sQ + 49152 + off, vs + (size_t)r * KD_ + cb * 8);
        }
        CP_COMMIT();
    }

    // ---- load Q tile [128 x 128] into swizzled smem
    {
        const uint4* src = (const uint4*)(Qb + mbase + (size_t)q0 * KD_);
        #pragma unroll
        for (int it = 0; it < 8; it++) {
            int idx = it * 256 + tid;
            int r = idx >> 4, cb = idx & 15;
            uint4 v = src[idx];
            *(uint4*)(smc + r * 256 + ((cb ^ (r & 7)) << 4)) = v;
        }
    }
    __syncthreads();

    // ---- extract Q A-frags
    uint32_t qa[8][4];
    {
        const int mi = l >> 3;
        const int rr = w * 16 + (mi & 1) * 8 + (l & 7);
        #pragma unroll
        for (int kc = 0; kc < 8; kc++) {
            const int cb = kc * 2 + (mi >> 1);
            LDMATRIX_X4(qa[kc][0], qa[kc][1], qa[kc][2], qa[kc][3],
                        sQ + rr * 256 + ((cb ^ (rr & 7)) << 4));
        }
    }

    float oacc[16][4] = {};
    float lsum0 = 0.0f, lsum1 = 0.0f;
    const int r0g = q0 + w * 16 + (l >> 2);
    const int r1g = r0g + 8;

    for (int kt = 0; kt < ntiles; kt++) {
        __syncthreads();   // prior compute done (protects buf (kt+1)&1)
        if (kt + 1 < ntiles) {
            const int s1 = (kt + 1) * BN;
            const uint32_t base = sQ + 32768 + ((kt + 1) & 1) * 32768;
            const __half* ks = Kb + mbase + (size_t)s1 * KD_;
            const __half* vs = Vb + mbase + (size_t)s1 * KD_;
            #pragma unroll
            for (int it = 0; it < 4; it++) {
                int idx = it * 256 + tid;
                int r = idx >> 4, cb = idx & 15;
                int off = r * 256 + ((cb ^ (r & 7)) << 4);
                CP_ASYNC16(base + off,         ks + (size_t)r * KD_ + cb * 8);
                CP_ASYNC16(base + 16384 + off, vs + (size_t)r * KD_ + cb * 8);
            }
            CP_COMMIT();
            cp_wait<1>();
        } else {
            cp_wait<0>();
        }
        __syncthreads();

        const uint32_t sK = sQ + 32768 + (kt & 1) * 32768;
        const uint32_t sV = sK + 16384;
        const int s0 = kt * BN;

        // ---- S = Q K^T  (log2-domain logits)
        float sacc[8][4] = {};
        {
            const int mi = l >> 3;
            #pragma unroll
            for (int kc = 0; kc < 8; kc++) {
                #pragma unroll
                for (int j = 0; j < 8; j += 2) {
                    const int nr = (j + (mi >> 1)) * 8 + (l & 7);
                    const int cb = kc * 2 + (mi & 1);
                    uint32_t b0, b1, b2, b3;
                    LDMATRIX_X4(b0, b1, b2, b3, sK + nr * 256 + ((cb ^ (nr & 7)) << 4));
                    MMA_16816(sacc[j],     qa[kc], b0, b1);
                    MMA_16816(sacc[j + 1], qa[kc], b2, b3);
                }
            }
        }

        // ---- mask + ex2.f16x2 -> P A-frags (one MUFU per 2 values)
        uint32_t pa[4][4];
        {
            const int cb0 = s0 + 2 * (l & 3);
            #pragma unroll
            for (int j = 0; j < 8; j++) {
                const int c0 = cb0 + 8 * j, c1 = c0 + 1;
                float m00 = (c0 <= r0g) ? sacc[j][0] : -60.0f;
                float m01 = (c1 <= r0g) ? sacc[j][1] : -60.0f;
                float m10 = (c0 <= r1g) ? sacc[j][2] : -60.0f;
                float m11 = (c1 <= r1g) ? sacc[j][3] : -60.0f;
                __half2 ha = __floats2half2_rn(m00, m01);
                __half2 hb = __floats2half2_rn(m10, m11);
                uint32_t ua, ub;
                asm("ex2.approx.f16x2 %0, %1;" : "=r"(ua) : "r"(*(uint32_t*)&ha));
                asm("ex2.approx.f16x2 %0, %1;" : "=r"(ub) : "r"(*(uint32_t*)&hb));
                float2 fa = __half22float2(*(__half2*)&ua);
                float2 fb = __half22float2(*(__half2*)&ub);
                lsum0 += fa.x + fa.y;
                lsum1 += fb.x + fb.y;
                const int kc2 = j >> 1, hi = (j & 1) * 2;
                pa[kc2][hi + 0] = ua;
                pa[kc2][hi + 1] = ub;
            }
        }

        // ---- O += P V
        {
            const int mi = l >> 3;
            #pragma unroll
            for (int kc2 = 0; kc2 < 4; kc2++) {
                #pragma unroll
                for (int j = 0; j < 16; j += 2) {
                    const int sr = kc2 * 16 + (mi & 1) * 8 + (l & 7);
                    const int cb = j + (mi >> 1);
                    uint32_t b0, b1, b2, b3;
                    LDMATRIX_X4_T(b0, b1, b2, b3, sV + sr * 256 + ((cb ^ (sr & 7)) << 4));
                    MMA_16816(oacc[j],     pa[kc2], b0, b1);
                    MMA_16816(oacc[j + 1], pa[kc2], b2, b3);
                }
            }
        }
    }

    // ---- epilogue
    lsum0 += __shfl_xor_sync(0xffffffffu, lsum0, 1);
    lsum0 += __shfl_xor_sync(0xffffffffu, lsum0, 2);
    lsum1 += __shfl_xor_sync(0xffffffffu, lsum1, 1);
    lsum1 += __shfl_xor_sync(0xffffffffu, lsum1, 2);
    const float li0 = 1.0f / lsum0, li1 = 1.0f / lsum1;

    const int b = m >> 3, h = m & 7;
    __half* base0 = Ph + ((size_t)b * T_ + r0g) * C_ + h * KD_ + 2 * (l & 3);
    __half* base1 = Ph + ((size_t)b * T_ + r1g) * C_ + h * KD_ + 2 * (l & 3);
    #pragma unroll
    for (int j = 0; j < 16; j++) {
        *(__half2*)(base0 + 8 * j) = __floats2half2_rn(oacc[j][0] * li0, oacc[j][1] * li0);
        *(__half2*)(base1 + 8 * j) = __floats2half2_rn(oacc[j][2] * li1, oacc[j][3] * li1);
    }
}

// ===========================================================================
extern "C" void kernel_launch(void* const* d_in, const int* in_sizes, int n_in,
                              void* d_out, int out_size)
{
    const float* x  = (const float*)d_in[0];
    const float* Wq = (const float*)d_in[1];
    const float* bq = (const float*)d_in[2];
    const float* Wk = (const float*)d_in[3];
    const float* bk = (const float*)d_in[4];
    const float* Wv = (const float*)d_in[5];
    const float* Wu = (const float*)d_in[6];
    const float* bu = (const float*)d_in[7];
    float* out = (float*)d_out;

    __half *xh, *wq5, *wk5, *wv, *wu, *qp, *kp, *vp, *ph;
    float* pacc;
    cudaGetSymbolAddress((void**)&xh,   g_xh);
    cudaGetSymbolAddress((void**)&wq5,  g_Wq5);
    cudaGetSymbolAddress((void**)&wk5,  g_Wk5);
    cudaGetSymbolAddress((void**)&wv,   g_Wv);
    cudaGetSymbolAddress((void**)&wu,   g_Wu);
    cudaGetSymbolAddress((void**)&qp,   g_Qh);
    cudaGetSymbolAddress((void**)&kp,   g_Kh);
    cudaGetSymbolAddress((void**)&vp,   g_Vh);
    cudaGetSymbolAddress((void**)&ph,   g_Ph);
    cudaGetSymbolAddress((void**)&pacc, g_acc);

    cudaFuncSetAttribute(attn_mma_kernel, cudaFuncAttributeMaxDynamicSharedMemorySize, ATTN_SMEM);
    cudaFuncSetAttribute(qkconv_kernel, cudaFuncAttributeMaxDynamicSharedMemorySize, QK_SMEM);
    cudaFuncSetAttribute((gemm16_kernel<1, 1, 0, 128, 1024, false, 1>),
                         cudaFuncAttributeMaxDynamicSharedMemorySize, 65536);
    cudaFuncSetAttribute(proj_partial_kernel, cudaFuncAttributeMaxDynamicSharedMemorySize, 65536);

    // 1/128^0.25 * sqrt(log2(e))  -> S lands in log2 domain
    const float qk_scale = 0.3570958376f;

    // ---- fused prepack (1 launch)
    pack_all_kernel<<<N_PACK / 256, 256>>>(x, Wq, Wk, Wv, Wu, xh, wq5, wk5, wv, wu);

    // ---- Q+K conv (merged, deep-pipelined), V conv
    dim3 gqk(T_ / 128, 16, B_);
    qkconv_kernel<<<gqk, 256, QK_SMEM>>>(xh, wq5, wk5, bq, bk, qp, kp, qk_scale);
    dim3 gv(T_ / 128, C_ / 128, B_);
    gemm16_kernel<1, 1, 0, 128, 1024, false, 1><<<gv, 256, 65536>>>(xh, wv, nullptr, vp, 1.0f);

    // ---- attention (1D grid, heavy q-tiles first globally)
    attn_mma_kernel<<<512, 256, ATTN_SMEM>>>(qp, kp, vp, ph);

    // ---- output projection: split-K partials + reduce
    dim3 gp(T_ / 128, PSPLIT, B_);
    proj_partial_kernel<<<gp, 256, 65536>>>(ph, wu, pacc);
    proj_reduce_kernel<<<(B_ * T_ * KD_) / 256, 256>>>(pacc, bu, out);
}

// round 9
// speedup vs baseline: 7.2574x; 1.0683x over previous
#include <cuda_runtime.h>
#include <cuda_fp16.h>
#include <cstdint>
#include <cstddef>

// Problem constants
#define B_ 4
#define T_ 2048
#define KD_ 128
#define H_ 8
#define C_ 1024   // KD_*H_
#define PSPLIT 4

// Scratch (device globals; no allocation allowed)
__device__ __align__(256) __half g_xh [(size_t)B_ * T_ * KD_];    // x fp16 [b][t][cin]
__device__ __align__(256) __half g_Wq5[(size_t)5 * C_ * KD_];     // [tap][cout][cin]
__device__ __align__(256) __half g_Wk5[(size_t)5 * C_ * KD_];
__device__ __align__(256) __half g_Wv [(size_t)C_ * KD_];         // [cout][cin]
__device__ __align__(256) __half g_Wu [(size_t)KD_ * C_];         // [cout][f]
__device__ __align__(256) __half g_Qh [(size_t)32 * T_ * KD_];    // [m][t'][d] flat view
__device__ __align__(256) __half g_Kh [(size_t)32 * T_ * KD_];
__device__ __align__(256) __half g_Vh [(size_t)32 * T_ * KD_];
__device__ __align__(256) __half g_Ph [(size_t)B_ * T_ * C_];     // attn out [b][t][f]
__device__ __align__(256) float  g_acc[(size_t)PSPLIT * B_ * T_ * KD_];  // proj partials

__device__ __forceinline__ uint32_t smem_to_u32(const void* p) {
    uint32_t a;
    asm("{ .reg .u64 t; cvta.to.shared.u64 t, %1; cvt.u32.u64 %0, t; }" : "=r"(a) : "l"(p));
    return a;
}

#define LDMATRIX_X4(r0, r1, r2, r3, addr) \
    asm volatile("ldmatrix.sync.aligned.m8n8.x4.shared.b16 {%0,%1,%2,%3}, [%4];" \
        : "=r"(r0), "=r"(r1), "=r"(r2), "=r"(r3) : "r"(addr))
#define LDMATRIX_X4_T(r0, r1, r2, r3, addr) \
    asm volatile("ldmatrix.sync.aligned.m8n8.x4.trans.shared.b16 {%0,%1,%2,%3}, [%4];" \
        : "=r"(r0), "=r"(r1), "=r"(r2), "=r"(r3) : "r"(addr))
#define MMA_16816(c, a, b0v, b1v) \
    asm volatile("mma.sync.aligned.m16n8k16.row.col.f32.f16.f16.f32 " \
        "{%0,%1,%2,%3},{%4,%5,%6,%7},{%8,%9},{%0,%1,%2,%3};" \
        : "+f"((c)[0]), "+f"((c)[1]), "+f"((c)[2]), "+f"((c)[3]) \
        : "r"((a)[0]), "r"((a)[1]), "r"((a)[2]), "r"((a)[3]), "r"(b0v), "r"(b1v))

#define CP_ASYNC16(dst, src) \
    asm volatile("cp.async.cg.shared.global [%0], [%1], 16;" :: "r"(dst), "l"(src))
#define CP_COMMIT() asm volatile("cp.async.commit_group;" ::: "memory")
template<int N> __device__ __forceinline__ void cp_wait() {
    asm volatile("cp.async.wait_group %0;" :: "n"(N) : "memory");
}

__device__ __forceinline__ float silu_f(float y) { return y / (1.0f + __expf(-y)); }

// ===========================================================================
// Fused prepack: x->fp16, Wq/Wk tap-major fp16, Wv/Wu fp16.
// ===========================================================================
#define N_X  (B_ * T_ * KD_)        // 1048576
#define N_W5 (5 * C_ * KD_)         // 655360
#define N_WV (C_ * KD_)             // 131072
#define N_WU (KD_ * C_)             // 131072
#define N_PACK (N_X + 2 * N_W5 + N_WV + N_WU)

__global__ void pack_all_kernel(
    const float* __restrict__ x, const float* __restrict__ Wq,
    const float* __restrict__ Wk, const float* __restrict__ Wv,
    const float* __restrict__ Wu,
    __half* __restrict__ xh, __half* __restrict__ wq5, __half* __restrict__ wk5,
    __half* __restrict__ wv, __half* __restrict__ wu)
{
    int i = blockIdx.x * 256 + threadIdx.x;
    if (i < N_X) { xh[i] = __float2half(x[i]); return; }
    i -= N_X;
    if (i < N_W5) {
        int cin = i & 127, c = (i >> 7) & 1023, j = i >> 17;
        wq5[i] = __float2half(Wq[((c << 7) + cin) * 5 + j]);
        return;
    }
    i -= N_W5;
    if (i < N_W5) {
        int cin = i & 127, c = (i >> 7) & 1023, j = i >> 17;
        wk5[i] = __float2half(Wk[((c << 7) + cin) * 5 + j]);
        return;
    }
    i -= N_W5;
    if (i < N_WV) { wv[i] = __float2half(Wv[i]); return; }
    i -= N_WV;
    if (i < N_WU) { wu[i] = __float2half(Wu[i]); }
}

// ===========================================================================
// Merged Q/K/V conv kernel. 128 threads / 4 warps; each warp owns M=32 rows
// (two 16-row groups sharing every B fragment -> half the B LDS traffic).
// CTA tile 128x128; A-resident, B double-buffered cp.async over taps.
// Smem 100352B -> 2 CTAs/SM for cross-CTA latency hiding.
// blockIdx.y: 0-7 Q tiles, 8-15 K tiles, 16-23 V tiles (1 tap, row offset 8).
// ===========================================================================
#define QKV_SMEM (34816 + 2 * 32768)

__global__ void __launch_bounds__(128, 2) qkvconv_kernel(
    const __half* __restrict__ A,
    const __half* __restrict__ Wq5, const __half* __restrict__ Wk5,
    const __half* __restrict__ Wv,
    const float* __restrict__ bq, const float* __restrict__ bk,
    __half* __restrict__ Qo, __half* __restrict__ Ko, __half* __restrict__ Vo,
    float qk_scale)
{
    extern __shared__ char smc[];
    const uint32_t sA  = smem_to_u32(smc);
    const uint32_t sB0 = sA + 34816;

    const int t0 = blockIdx.x * 128;
    const int cm = blockIdx.y;
    const int mat = cm >> 3;                 // 0=Q 1=K 2=V
    const int c0 = (cm & 7) * 128;
    const int b  = blockIdx.z;
    const __half* Bw  = (mat == 0) ? Wq5 : (mat == 1) ? Wk5 : Wv;
    const float* bias = (mat == 0) ? bq  : (mat == 1) ? bk  : nullptr;
    __half* out       = (mat == 0) ? Qo  : (mat == 1) ? Ko  : Vo;
    const float scale = (mat == 2) ? 1.0f : qk_scale;
    const int ntaps   = (mat == 2) ? 1 : 5;

    const int tid = threadIdx.x, w = tid >> 5, l = tid & 31;
    const int mi = l >> 3;

    // ---- prefetch B tap 0 into buf 0 (32KB / 128 thr = 16 x 16B each)
    #pragma unroll
    for (int it = 0; it < 16; it++) {
        int idx = it * 128 + tid;
        int r = idx >> 4, cb = idx & 15;
        CP_ASYNC16(sB0 + r * 256 + ((cb ^ (r & 7)) << 4),
                   Bw + ((size_t)(c0 + r)) * 128 + cb * 8);
    }
    CP_COMMIT();

    // ---- load A rows t0-8 .. t0+127 (136 rows), guarded
    #pragma unroll
    for (int it = 0; it < 17; it++) {
        int idx = it * 128 + tid;
        if (idx < 136 * 16) {
            int r = idx >> 4, cb = idx & 15;
            int tg = t0 + r - 8;
            uint4 v = make_uint4(0u, 0u, 0u, 0u);
            if (tg >= 0 && tg < T_)
                v = *(const uint4*)(A + ((size_t)b * T_ + tg) * 128 + cb * 8);
            *(uint4*)(smc + r * 256 + ((cb ^ (r & 7)) << 4)) = v;
        }
    }

    float cacc[2][16][4] = {};

    #pragma unroll 1
    for (int j = 0; j < ntaps; j++) {
        __syncthreads();   // prior compute done (protects buf (j+1)&1); A stores for j=0
        if (j + 1 < ntaps) {
            const uint32_t sBn = sB0 + ((j + 1) & 1) * 32768;
            #pragma unroll
            for (int it = 0; it < 16; it++) {
                int idx = it * 128 + tid;
                int r = idx >> 4, cb = idx & 15;
                CP_ASYNC16(sBn + r * 256 + ((cb ^ (r & 7)) << 4),
                           Bw + ((size_t)(j + 1) * C_ + c0 + r) * 128 + cb * 8);
            }
            CP_COMMIT();
            cp_wait<1>();
        } else {
            cp_wait<0>();
        }
        __syncthreads();

        const uint32_t sB = sB0 + (j & 1) * 32768;
        const int rowoff = (mat == 2) ? 8 : 2 * j;  // A row = out row + rowoff
        #pragma unroll
        for (int kc = 0; kc < 8; kc++) {
            uint32_t a4[2][4];
            #pragma unroll
            for (int rg = 0; rg < 2; rg++) {
                const int rr = w * 32 + rg * 16 + (mi & 1) * 8 + (l & 7) + rowoff;
                const int cba = kc * 2 + (mi >> 1);
                LDMATRIX_X4(a4[rg][0], a4[rg][1], a4[rg][2], a4[rg][3],
                            sA + rr * 256 + ((cba ^ (rr & 7)) << 4));
            }
            #pragma unroll
            for (int jn = 0; jn < 16; jn += 2) {
                const int nr = (jn + (mi >> 1)) * 8 + (l & 7);
                const int cbb = kc * 2 + (mi & 1);
                uint32_t b0, b1, b2, b3;
                LDMATRIX_X4(b0, b1, b2, b3, sB + nr * 256 + ((cbb ^ (nr & 7)) << 4));
                MMA_16816(cacc[0][jn],     a4[0], b0, b1);
                MMA_16816(cacc[0][jn + 1], a4[0], b2, b3);
                MMA_16816(cacc[1][jn],     a4[1], b0, b1);
                MMA_16816(cacc[1][jn + 1], a4[1], b2, b3);
            }
        }
    }

    // ---- epilogue: bias + silu + scale, remapped fp16 store [b][t][h][k]
    #pragma unroll
    for (int rg = 0; rg < 2; rg++) {
        const int tr0 = t0 + w * 32 + rg * 16 + (l >> 2);
        const int tr1 = tr0 + 8;
        #pragma unroll
        for (int jn = 0; jn < 16; jn++) {
            const int c = c0 + 8 * jn + 2 * (l & 3);
            const float bv0 = (mat < 2) ? bias[c] : 0.0f;
            const float bv1 = (mat < 2) ? bias[c + 1] : 0.0f;
            float s00 = silu_f(cacc[rg][jn][0] + bv0) * scale;
            float s01 = silu_f(cacc[rg][jn][1] + bv1) * scale;
            float s10 = silu_f(cacc[rg][jn][2] + bv0) * scale;
            float s11 = silu_f(cacc[rg][jn][3] + bv1) * scale;
            out[(((size_t)b * T_ + tr0) * H_ + (c & 7)) * KD_ + (c >> 3)]             = __float2half(s00);
            out[(((size_t)b * T_ + tr0) * H_ + ((c + 1) & 7)) * KD_ + ((c + 1) >> 3)] = __float2half(s01);
            out[(((size_t)b * T_ + tr1) * H_ + (c & 7)) * KD_ + (c >> 3)]             = __float2half(s10);
            out[(((size_t)b * T_ + tr1) * H_ + ((c + 1) & 7)) * KD_ + ((c + 1) >> 3)] = __float2half(s11);
        }
    }
}

// ===========================================================================
// Projection with split-K: partial GEMM (no act) + reduce(bias+silu).
// ===========================================================================
__global__ void __launch_bounds__(256, 1) proj_partial_kernel(
    const __half* __restrict__ A, const __half* __restrict__ Bw,
    float* __restrict__ part)
{
    extern __shared__ char smc[];
    const uint32_t sA = smem_to_u32(smc);
    const uint32_t sB = sA + 32768;

    const int t0 = blockIdx.x * 128;
    const int sp = blockIdx.y;
    const int b  = blockIdx.z;
    const int tid = threadIdx.x, w = tid >> 5, l = tid & 31;
    const int mi = l >> 3;

    float cacc[16][4] = {};

    #pragma unroll 1
    for (int ch = 0; ch < 2; ch++) {
        const int cin0 = sp * 256 + ch * 128;
        __syncthreads();
        #pragma unroll
        for (int it = 0; it < 8; it++) {
            int idx = it * 256 + tid;
            int r = idx >> 4, cb = idx & 15;
            uint4 v = *(const uint4*)(A + ((size_t)b * T_ + t0 + r) * C_ + cin0 + cb * 8);
            *(uint4*)(smc + r * 256 + ((cb ^ (r & 7)) << 4)) = v;
        }
        #pragma unroll
        for (int it = 0; it < 8; it++) {
            int idx = it * 256 + tid;
            int r = idx >> 4, cb = idx & 15;
            uint4 v = *(const uint4*)(Bw + (size_t)r * C_ + cin0 + cb * 8);
            *(uint4*)(smc + 32768 + r * 256 + ((cb ^ (r & 7)) << 4)) = v;
        }
        __syncthreads();
        #pragma unroll
        for (int kc = 0; kc < 8; kc++) {
            uint32_t a4[4];
            const int rr = w * 16 + (mi & 1) * 8 + (l & 7);
            const int cba = kc * 2 + (mi >> 1);
            LDMATRIX_X4(a4[0], a4[1], a4[2], a4[3],
                        sA + rr * 256 + ((cba ^ (rr & 7)) << 4));
            #pragma unroll
            for (int jn = 0; jn < 16; jn += 2) {
                const int nr = (jn + (mi >> 1)) * 8 + (l & 7);
                const int cbb = kc * 2 + (mi & 1);
                uint32_t b0, b1, b2, b3;
                LDMATRIX_X4(b0, b1, b2, b3, sB + nr * 256 + ((cbb ^ (nr & 7)) << 4));
                MMA_16816(cacc[jn],     a4, b0, b1);
                MMA_16816(cacc[jn + 1], a4, b2, b3);
            }
        }
    }

    const int tr0 = t0 + w * 16 + (l >> 2);
    const int tr1 = tr0 + 8;
    float* dst = part + (size_t)sp * (B_ * T_ * KD_);
    #pragma unroll
    for (int jn = 0; jn < 16; jn++) {
        const int c = 8 * jn + 2 * (l & 3);
        *(float2*)(dst + ((size_t)b * T_ + tr0) * KD_ + c) = make_float2(cacc[jn][0], cacc[jn][1]);
        *(float2*)(dst + ((size_t)b * T_ + tr1) * KD_ + c) = make_float2(cacc[jn][2], cacc[jn][3]);
    }
}

__global__ void proj_reduce_kernel(const float* __restrict__ part,
                                   const float* __restrict__ bu,
                                   float* __restrict__ out)
{
    const int i = blockIdx.x * 256 + threadIdx.x;   // over B*T*128
    const int c = i & 127;
    const int S = B_ * T_ * KD_;
    float s = part[i] + part[i + S] + part[i + 2 * S] + part[i + 3 * S];
    out[i] = silu_f(s + bu[c]);
}

// ===========================================================================
// Flash attention via mma.sync; K/V double-buffered cp.async.
// Q/K carry sqrt(log2e) factor -> S in log2 domain; exp via ex2.f16x2.
// ===========================================================================
#define BM 128
#define BN 64
#define ATTN_SMEM 98304

__global__ void __launch_bounds__(256, 1)
attn_mma_kernel(const __half* __restrict__ Qb, const __half* __restrict__ Kb,
                const __half* __restrict__ Vb, __half* __restrict__ Ph)
{
    extern __shared__ char smc[];
    const uint32_t sQ = smem_to_u32(smc);

    const int tid = threadIdx.x, w = tid >> 5, l = tid & 31;
    const int bid = blockIdx.x;
    const int bi  = 15 - (bid >> 5);       // q-tile index, heavy (15) first
    const int m   = bid & 31;
    const int q0  = bi * BM;
    const size_t mbase = (size_t)m * T_ * KD_;
    const int ntiles = 2 * bi + 2;

    // ---- prefetch K/V tile 0 into buf 0
    {
        const __half* ks = Kb + mbase;
        const __half* vs = Vb + mbase;
        #pragma unroll
        for (int it = 0; it < 4; it++) {
            int idx = it * 256 + tid;
            int r = idx >> 4, cb = idx & 15;
            int off = r * 256 + ((cb ^ (r & 7)) << 4);
            CP_ASYNC16(sQ + 32768 + off, ks + (size_t)r * KD_ + cb * 8);
            CP_ASYNC16(sQ + 49152 + off, vs + (size_t)r * KD_ + cb * 8);
        }
        CP_COMMIT();
    }

    // ---- load Q tile [128 x 128] into swizzled smem
    {
        const uint4* src = (const uint4*)(Qb + mbase + (size_t)q0 * KD_);
        #pragma unroll
        for (int it = 0; it < 8; it++) {
            int idx = it * 256 + tid;
            int r = idx >> 4, cb = idx & 15;
            uint4 v = src[idx];
            *(uint4*)(smc + r * 256 + ((cb ^ (r & 7)) << 4)) = v;
        }
    }
    __syncthreads();

    // ---- extract Q A-frags
    uint32_t qa[8][4];
    {
        const int mi = l >> 3;
        const int rr = w * 16 + (mi & 1) * 8 + (l & 7);
        #pragma unroll
        for (int kc = 0; kc < 8; kc++) {
            const int cb = kc * 2 + (mi >> 1);
            LDMATRIX_X4(qa[kc][0], qa[kc][1], qa[kc][2], qa[kc][3],
                        sQ + rr * 256 + ((cb ^ (rr & 7)) << 4));
        }
    }

    float oacc[16][4] = {};
    float lsum0 = 0.0f, lsum1 = 0.0f;
    const int r0g = q0 + w * 16 + (l >> 2);
    const int r1g = r0g + 8;

    for (int kt = 0; kt < ntiles; kt++) {
        __syncthreads();   // prior compute done (protects buf (kt+1)&1)
        if (kt + 1 < ntiles) {
            const int s1 = (kt + 1) * BN;
            const uint32_t base = sQ + 32768 + ((kt + 1) & 1) * 32768;
            const __half* ks = Kb + mbase + (size_t)s1 * KD_;
            const __half* vs = Vb + mbase + (size_t)s1 * KD_;
            #pragma unroll
            for (int it = 0; it < 4; it++) {
                int idx = it * 256 + tid;
                int r = idx >> 4, cb = idx & 15;
                int off = r * 256 + ((cb ^ (r & 7)) << 4);
                CP_ASYNC16(base + off,         ks + (size_t)r * KD_ + cb * 8);
                CP_ASYNC16(base + 16384 + off, vs + (size_t)r * KD_ + cb * 8);
            }
            CP_COMMIT();
            cp_wait<1>();
        } else {
            cp_wait<0>();
        }
        __syncthreads();

        const uint32_t sK = sQ + 32768 + (kt & 1) * 32768;
        const uint32_t sV = sK + 16384;
        const int s0 = kt * BN;

        // ---- S = Q K^T  (log2-domain logits)
        float sacc[8][4] = {};
        {
            const int mi = l >> 3;
            #pragma unroll
            for (int kc = 0; kc < 8; kc++) {
                #pragma unroll
                for (int j = 0; j < 8; j += 2) {
                    const int nr = (j + (mi >> 1)) * 8 + (l & 7);
                    const int cb = kc * 2 + (mi & 1);
                    uint32_t b0, b1, b2, b3;
                    LDMATRIX_X4(b0, b1, b2, b3, sK + nr * 256 + ((cb ^ (nr & 7)) << 4));
                    MMA_16816(sacc[j],     qa[kc], b0, b1);
                    MMA_16816(sacc[j + 1], qa[kc], b2, b3);
                }
            }
        }

        // ---- mask + ex2.f16x2 -> P A-frags (one MUFU per 2 values)
        uint32_t pa[4][4];
        {
            const int cb0 = s0 + 2 * (l & 3);
            #pragma unroll
            for (int j = 0; j < 8; j++) {
                const int c0 = cb0 + 8 * j, c1 = c0 + 1;
                float m00 = (c0 <= r0g) ? sacc[j][0] : -60.0f;
                float m01 = (c1 <= r0g) ? sacc[j][1] : -60.0f;
                float m10 = (c0 <= r1g) ? sacc[j][2] : -60.0f;
                float m11 = (c1 <= r1g) ? sacc[j][3] : -60.0f;
                __half2 ha = __floats2half2_rn(m00, m01);
                __half2 hb = __floats2half2_rn(m10, m11);
                uint32_t ua, ub;
                asm("ex2.approx.f16x2 %0, %1;" : "=r"(ua) : "r"(*(uint32_t*)&ha));
                asm("ex2.approx.f16x2 %0, %1;" : "=r"(ub) : "r"(*(uint32_t*)&hb));
                float2 fa = __half22float2(*(__half2*)&ua);
                float2 fb = __half22float2(*(__half2*)&ub);
                lsum0 += fa.x + fa.y;
                lsum1 += fb.x + fb.y;
                const int kc2 = j >> 1, hi = (j & 1) * 2;
                pa[kc2][hi + 0] = ua;
                pa[kc2][hi + 1] = ub;
            }
        }

        // ---- O += P V
        {
            const int mi = l >> 3;
            #pragma unroll
            for (int kc2 = 0; kc2 < 4; kc2++) {
                #pragma unroll
                for (int j = 0; j < 16; j += 2) {
                    const int sr = kc2 * 16 + (mi & 1) * 8 + (l & 7);
                    const int cb = j + (mi >> 1);
                    uint32_t b0, b1, b2, b3;
                    LDMATRIX_X4_T(b0, b1, b2, b3, sV + sr * 256 + ((cb ^ (sr & 7)) << 4));
                    MMA_16816(oacc[j],     pa[kc2], b0, b1);
                    MMA_16816(oacc[j + 1], pa[kc2], b2, b3);
                }
            }
        }
    }

    // ---- epilogue
    lsum0 += __shfl_xor_sync(0xffffffffu, lsum0, 1);
    lsum0 += __shfl_xor_sync(0xffffffffu, lsum0, 2);
    lsum1 += __shfl_xor_sync(0xffffffffu, lsum1, 1);
    lsum1 += __shfl_xor_sync(0xffffffffu, lsum1, 2);
    const float li0 = 1.0f / lsum0, li1 = 1.0f / lsum1;

    const int b = m >> 3, h = m & 7;
    __half* base0 = Ph + ((size_t)b * T_ + r0g) * C_ + h * KD_ + 2 * (l & 3);
    __half* base1 = Ph + ((size_t)b * T_ + r1g) * C_ + h * KD_ + 2 * (l & 3);
    #pragma unroll
    for (int j = 0; j < 16; j++) {
        *(__half2*)(base0 + 8 * j) = __floats2half2_rn(oacc[j][0] * li0, oacc[j][1] * li0);
        *(__half2*)(base1 + 8 * j) = __floats2half2_rn(oacc[j][2] * li1, oacc[j][3] * li1);
    }
}

// ===========================================================================
extern "C" void kernel_launch(void* const* d_in, const int* in_sizes, int n_in,
                              void* d_out, int out_size)
{
    const float* x  = (const float*)d_in[0];
    const float* Wq = (const float*)d_in[1];
    const float* bq = (const float*)d_in[2];
    const float* Wk = (const float*)d_in[3];
    const float* bk = (const float*)d_in[4];
    const float* Wv = (const float*)d_in[5];
    const float* Wu = (const float*)d_in[6];
    const float* bu = (const float*)d_in[7];
    float* out = (float*)d_out;

    __half *xh, *wq5, *wk5, *wv, *wu, *qp, *kp, *vp, *ph;
    float* pacc;
    cudaGetSymbolAddress((void**)&xh,   g_xh);
    cudaGetSymbolAddress((void**)&wq5,  g_Wq5);
    cudaGetSymbolAddress((void**)&wk5,  g_Wk5);
    cudaGetSymbolAddress((void**)&wv,   g_Wv);
    cudaGetSymbolAddress((void**)&wu,   g_Wu);
    cudaGetSymbolAddress((void**)&qp,   g_Qh);
    cudaGetSymbolAddress((void**)&kp,   g_Kh);
    cudaGetSymbolAddress((void**)&vp,   g_Vh);
    cudaGetSymbolAddress((void**)&ph,   g_Ph);
    cudaGetSymbolAddress((void**)&pacc, g_acc);

    cudaFuncSetAttribute(attn_mma_kernel, cudaFuncAttributeMaxDynamicSharedMemorySize, ATTN_SMEM);
    cudaFuncSetAttribute(qkvconv_kernel, cudaFuncAttributeMaxDynamicSharedMemorySize, QKV_SMEM);
    cudaFuncSetAttribute(proj_partial_kernel, cudaFuncAttributeMaxDynamicSharedMemorySize, 65536);

    // 1/128^0.25 * sqrt(log2(e))  -> S lands in log2 domain
    const float qk_scale = 0.3570958376f;

    // ---- fused prepack (1 launch)
    pack_all_kernel<<<N_PACK / 256, 256>>>(x, Wq, Wk, Wv, Wu, xh, wq5, wk5, wv, wu);

    // ---- merged Q/K/V conv
    dim3 gqkv(T_ / 128, 24, B_);
    qkvconv_kernel<<<gqkv, 128, QKV_SMEM>>>(xh, wq5, wk5, wv, bq, bk, qp, kp, vp, qk_scale);

    // ---- attention (1D grid, heavy q-tiles first globally)
    attn_mma_kernel<<<512, 256, ATTN_SMEM>>>(qp, kp, vp, ph);

    // ---- output projection: split-K partials + reduce
    dim3 gp(T_ / 128, PSPLIT, B_);
    proj_partial_kernel<<<gp, 256, 65536>>>(ph, wu, pacc);
    proj_reduce_kernel<<<(B_ * T_ * KD_) / 256, 256>>>(pacc, bu, out);
}

// round 10
// speedup vs baseline: 12.7323x; 1.7544x over previous
#include <cuda_runtime.h>
#include <cuda_fp16.h>
#include <cstdint>
#include <cstddef>

// Problem constants
#define B_ 4
#define T_ 2048
#define KD_ 128
#define H_ 8
#define C_ 1024   // KD_*H_
#define PSPLIT 4

// Scratch (device globals; no allocation allowed)
__device__ __align__(256) __half g_xh [(size_t)B_ * T_ * KD_];    // x fp16 [b][t][cin]
__device__ __align__(256) __half g_Wq5[(size_t)5 * C_ * KD_];     // [tap][f(perm)][cin]
__device__ __align__(256) __half g_Wk5[(size_t)5 * C_ * KD_];
__device__ __align__(256) __half g_Wv [(size_t)C_ * KD_];         // [f(perm)][cin]
__device__ __align__(256) __half g_Wu [(size_t)KD_ * C_];         // [cout][f]
__device__ __align__(256) __half g_Qh [(size_t)32 * T_ * KD_];    // [b][t][f] == [m][t'][d]
__device__ __align__(256) __half g_Kh [(size_t)32 * T_ * KD_];
__device__ __align__(256) __half g_Vh [(size_t)32 * T_ * KD_];
__device__ __align__(256) __half g_Ph [(size_t)B_ * T_ * C_];     // attn out [b][t][f]
__device__ __align__(256) float  g_acc[(size_t)PSPLIT * B_ * T_ * KD_];  // proj partials

__device__ __forceinline__ uint32_t smem_to_u32(const void* p) {
    uint32_t a;
    asm("{ .reg .u64 t; cvta.to.shared.u64 t, %1; cvt.u32.u64 %0, t; }" : "=r"(a) : "l"(p));
    return a;
}

#define LDMATRIX_X4(r0, r1, r2, r3, addr) \
    asm volatile("ldmatrix.sync.aligned.m8n8.x4.shared.b16 {%0,%1,%2,%3}, [%4];" \
        : "=r"(r0), "=r"(r1), "=r"(r2), "=r"(r3) : "r"(addr))
#define LDMATRIX_X4_T(r0, r1, r2, r3, addr) \
    asm volatile("ldmatrix.sync.aligned.m8n8.x4.trans.shared.b16 {%0,%1,%2,%3}, [%4];" \
        : "=r"(r0), "=r"(r1), "=r"(r2), "=r"(r3) : "r"(addr))
#define MMA_16816(c, a, b0v, b1v) \
    asm volatile("mma.sync.aligned.m16n8k16.row.col.f32.f16.f16.f32 " \
        "{%0,%1,%2,%3},{%4,%5,%6,%7},{%8,%9},{%0,%1,%2,%3};" \
        : "+f"((c)[0]), "+f"((c)[1]), "+f"((c)[2]), "+f"((c)[3]) \
        : "r"((a)[0]), "r"((a)[1]), "r"((a)[2]), "r"((a)[3]), "r"(b0v), "r"(b1v))

#define CP_ASYNC16(dst, src) \
    asm volatile("cp.async.cg.shared.global [%0], [%1], 16;" :: "r"(dst), "l"(src))
#define CP_COMMIT() asm volatile("cp.async.commit_group;" ::: "memory")
template<int N> __device__ __forceinline__ void cp_wait() {
    asm volatile("cp.async.wait_group %0;" :: "n"(N) : "memory");
}

__device__ __forceinline__ float silu_f(float y) { return y / (1.0f + __expf(-y)); }

// ===========================================================================
// Fused prepack. Wq/Wk/Wv cout rows are PERMUTED: row f holds original
// channel c = ((f&127)<<3)|(f>>7)  (f = h*128 + k), so the conv's output
// channels come out directly in [b][t][f] order (coalesced stores).
// ===========================================================================
#define N_X  (B_ * T_ * KD_)        // 1048576
#define N_W5 (5 * C_ * KD_)         // 655360
#define N_WV (C_ * KD_)             // 131072
#define N_WU (KD_ * C_)             // 131072
#define N_PACK (N_X + 2 * N_W5 + N_WV + N_WU)

__global__ void pack_all_kernel(
    const float* __restrict__ x, const float* __restrict__ Wq,
    const float* __restrict__ Wk, const float* __restrict__ Wv,
    const float* __restrict__ Wu,
    __half* __restrict__ xh, __half* __restrict__ wq5, __half* __restrict__ wk5,
    __half* __restrict__ wv, __half* __restrict__ wu)
{
    int i = blockIdx.x * 256 + threadIdx.x;
    if (i < N_X) { xh[i] = __float2half(x[i]); return; }
    i -= N_X;
    if (i < N_W5) {
        int cin = i & 127, f = (i >> 7) & 1023, j = i >> 17;
        int c = ((f & 127) << 3) | (f >> 7);
        wq5[i] = __float2half(Wq[((c << 7) + cin) * 5 + j]);
        return;
    }
    i -= N_W5;
    if (i < N_W5) {
        int cin = i & 127, f = (i >> 7) & 1023, j = i >> 17;
        int c = ((f & 127) << 3) | (f >> 7);
        wk5[i] = __float2half(Wk[((c << 7) + cin) * 5 + j]);
        return;
    }
    i -= N_W5;
    if (i < N_WV) {
        int cin = i & 127, f = i >> 7;
        int c = ((f & 127) << 3) | (f >> 7);
        wv[i] = __float2half(Wv[(c << 7) + cin]);
        return;
    }
    i -= N_WV;
    if (i < N_WU) { wu[i] = __float2half(Wu[i]); }
}

// ===========================================================================
// Merged Q/K/V conv kernel. 128 threads / 4 warps, M=32 rows per warp.
// A-resident, B double-buffered cp.async over taps; permuted weights give
// COALESCED __half2 epilogue stores into [b][t][f].
// blockIdx.y: 0-7 Q tiles, 8-15 K tiles, 16-23 V tiles (1 tap, row off 8).
// ===========================================================================
#define QKV_SMEM (34816 + 2 * 32768)

__global__ void __launch_bounds__(128, 2) qkvconv_kernel(
    const __half* __restrict__ A,
    const __half* __restrict__ Wq5, const __half* __restrict__ Wk5,
    const __half* __restrict__ Wv,
    const float* __restrict__ bq, const float* __restrict__ bk,
    __half* __restrict__ Qo, __half* __restrict__ Ko, __half* __restrict__ Vo,
    float qk_scale)
{
    extern __shared__ char smc[];
    const uint32_t sA  = smem_to_u32(smc);
    const uint32_t sB0 = sA + 34816;

    const int t0 = blockIdx.x * 128;
    const int cm = blockIdx.y;
    const int mat = cm >> 3;                 // 0=Q 1=K 2=V
    const int c0 = (cm & 7) * 128;           // f-tile base
    const int b  = blockIdx.z;
    const __half* Bw  = (mat == 0) ? Wq5 : (mat == 1) ? Wk5 : Wv;
    const float* bias = (mat == 0) ? bq  : (mat == 1) ? bk  : nullptr;
    __half* out       = (mat == 0) ? Qo  : (mat == 1) ? Ko  : Vo;
    const float scale = (mat == 2) ? 1.0f : qk_scale;
    const int ntaps   = (mat == 2) ? 1 : 5;

    const int tid = threadIdx.x, w = tid >> 5, l = tid & 31;
    const int mi = l >> 3;

    // ---- prefetch B tap 0 into buf 0 (32KB / 128 thr = 16 x 16B each)
    #pragma unroll
    for (int it = 0; it < 16; it++) {
        int idx = it * 128 + tid;
        int r = idx >> 4, cb = idx & 15;
        CP_ASYNC16(sB0 + r * 256 + ((cb ^ (r & 7)) << 4),
                   Bw + ((size_t)(c0 + r)) * 128 + cb * 8);
    }
    CP_COMMIT();

    // ---- load A rows t0-8 .. t0+127 (136 rows), guarded
    #pragma unroll
    for (int it = 0; it < 17; it++) {
        int idx = it * 128 + tid;
        if (idx < 136 * 16) {
            int r = idx >> 4, cb = idx & 15;
            int tg = t0 + r - 8;
            uint4 v = make_uint4(0u, 0u, 0u, 0u);
            if (tg >= 0 && tg < T_)
                v = *(const uint4*)(A + ((size_t)b * T_ + tg) * 128 + cb * 8);
            *(uint4*)(smc + r * 256 + ((cb ^ (r & 7)) << 4)) = v;
        }
    }

    float cacc[2][16][4] = {};

    #pragma unroll 1
    for (int j = 0; j < ntaps; j++) {
        __syncthreads();   // prior compute done (protects buf (j+1)&1); A stores for j=0
        if (j + 1 < ntaps) {
            const uint32_t sBn = sB0 + ((j + 1) & 1) * 32768;
            #pragma unroll
            for (int it = 0; it < 16; it++) {
                int idx = it * 128 + tid;
                int r = idx >> 4, cb = idx & 15;
                CP_ASYNC16(sBn + r * 256 + ((cb ^ (r & 7)) << 4),
                           Bw + ((size_t)(j + 1) * C_ + c0 + r) * 128 + cb * 8);
            }
            CP_COMMIT();
            cp_wait<1>();
        } else {
            cp_wait<0>();
        }
        __syncthreads();

        const uint32_t sB = sB0 + (j & 1) * 32768;
        const int rowoff = (mat == 2) ? 8 : 2 * j;  // A row = out row + rowoff
        #pragma unroll
        for (int kc = 0; kc < 8; kc++) {
            uint32_t a4[2][4];
            #pragma unroll
            for (int rg = 0; rg < 2; rg++) {
                const int rr = w * 32 + rg * 16 + (mi & 1) * 8 + (l & 7) + rowoff;
                const int cba = kc * 2 + (mi >> 1);
                LDMATRIX_X4(a4[rg][0], a4[rg][1], a4[rg][2], a4[rg][3],
                            sA + rr * 256 + ((cba ^ (rr & 7)) << 4));
            }
            #pragma unroll
            for (int jn = 0; jn < 16; jn += 2) {
                const int nr = (jn + (mi >> 1)) * 8 + (l & 7);
                const int cbb = kc * 2 + (mi & 1);
                uint32_t b0, b1, b2, b3;
                LDMATRIX_X4(b0, b1, b2, b3, sB + nr * 256 + ((cbb ^ (nr & 7)) << 4));
                MMA_16816(cacc[0][jn],     a4[0], b0, b1);
                MMA_16816(cacc[0][jn + 1], a4[0], b2, b3);
                MMA_16816(cacc[1][jn],     a4[1], b0, b1);
                MMA_16816(cacc[1][jn + 1], a4[1], b2, b3);
            }
        }
    }

    // ---- epilogue: bias(perm) + silu + scale, COALESCED half2 stores [b][t][f]
    #pragma unroll
    for (int rg = 0; rg < 2; rg++) {
        const int tr0 = t0 + w * 32 + rg * 16 + (l >> 2);
        const int tr1 = tr0 + 8;
        #pragma unroll
        for (int jn = 0; jn < 16; jn++) {
            const int f = c0 + 8 * jn + 2 * (l & 3);
            float bv0 = 0.0f, bv1 = 0.0f;
            if (mat < 2) {
                const int co = ((f & 127) << 3) | (f >> 7);   // original channel
                bv0 = bias[co];
                bv1 = bias[co + 8];                            // f+1 -> k+1 -> c+8
            }
            float s00 = silu_f(cacc[rg][jn][0] + bv0) * scale;
            float s01 = silu_f(cacc[rg][jn][1] + bv1) * scale;
            float s10 = silu_f(cacc[rg][jn][2] + bv0) * scale;
            float s11 = silu_f(cacc[rg][jn][3] + bv1) * scale;
            *(__half2*)(out + ((size_t)b * T_ + tr0) * C_ + f) = __floats2half2_rn(s00, s01);
            *(__half2*)(out + ((size_t)b * T_ + tr1) * C_ + f) = __floats2half2_rn(s10, s11);
        }
    }
}

// ===========================================================================
// Projection with split-K: partial GEMM (no act) + reduce(bias+silu).
// ===========================================================================
__global__ void __launch_bounds__(256, 1) proj_partial_kernel(
    const __half* __restrict__ A, const __half* __restrict__ Bw,
    float* __restrict__ part)
{
    extern __shared__ char smc[];
    const uint32_t sA = smem_to_u32(smc);
    const uint32_t sB = sA + 32768;

    const int t0 = blockIdx.x * 128;
    const int sp = blockIdx.y;
    const int b  = blockIdx.z;
    const int tid = threadIdx.x, w = tid >> 5, l = tid & 31;
    const int mi = l >> 3;

    float cacc[16][4] = {};

    #pragma unroll 1
    for (int ch = 0; ch < 2; ch++) {
        const int cin0 = sp * 256 + ch * 128;
        __syncthreads();
        #pragma unroll
        for (int it = 0; it < 8; it++) {
            int idx = it * 256 + tid;
            int r = idx >> 4, cb = idx & 15;
            uint4 v = *(const uint4*)(A + ((size_t)b * T_ + t0 + r) * C_ + cin0 + cb * 8);
            *(uint4*)(smc + r * 256 + ((cb ^ (r & 7)) << 4)) = v;
        }
        #pragma unroll
        for (int it = 0; it < 8; it++) {
            int idx = it * 256 + tid;
            int r = idx >> 4, cb = idx & 15;
            uint4 v = *(const uint4*)(Bw + (size_t)r * C_ + cin0 + cb * 8);
            *(uint4*)(smc + 32768 + r * 256 + ((cb ^ (r & 7)) << 4)) = v;
        }
        __syncthreads();
        #pragma unroll
        for (int kc = 0; kc < 8; kc++) {
            uint32_t a4[4];
            const int rr = w * 16 + (mi & 1) * 8 + (l & 7);
            const int cba = kc * 2 + (mi >> 1);
            LDMATRIX_X4(a4[0], a4[1], a4[2], a4[3],
                        sA + rr * 256 + ((cba ^ (rr & 7)) << 4));
            #pragma unroll
            for (int jn = 0; jn < 16; jn += 2) {
                const int nr = (jn + (mi >> 1)) * 8 + (l & 7);
                const int cbb = kc * 2 + (mi & 1);
                uint32_t b0, b1, b2, b3;
                LDMATRIX_X4(b0, b1, b2, b3, sB + nr * 256 + ((cbb ^ (nr & 7)) << 4));
                MMA_16816(cacc[jn],     a4, b0, b1);
                MMA_16816(cacc[jn + 1], a4, b2, b3);
            }
        }
    }

    const int tr0 = t0 + w * 16 + (l >> 2);
    const int tr1 = tr0 + 8;
    float* dst = part + (size_t)sp * (B_ * T_ * KD_);
    #pragma unroll
    for (int jn = 0; jn < 16; jn++) {
        const int c = 8 * jn + 2 * (l & 3);
        *(float2*)(dst + ((size_t)b * T_ + tr0) * KD_ + c) = make_float2(cacc[jn][0], cacc[jn][1]);
        *(float2*)(dst + ((size_t)b * T_ + tr1) * KD_ + c) = make_float2(cacc[jn][2], cacc[jn][3]);
    }
}

__global__ void proj_reduce_kernel(const float* __restrict__ part,
                                   const float* __restrict__ bu,
                                   float* __restrict__ out)
{
    const int i = blockIdx.x * 256 + threadIdx.x;   // over B*T*128
    const int c = i & 127;
    const int S = B_ * T_ * KD_;
    float s = part[i] + part[i + S] + part[i + 2 * S] + part[i + 3 * S];
    out[i] = silu_f(s + bu[c]);
}

// ===========================================================================
// Flash attention via mma.sync; K/V double-buffered cp.async.
// Q/K carry sqrt(log2e) factor -> S in log2 domain; exp via ex2.f16x2.
// ===========================================================================
#define BM 128
#define BN 64
#define ATTN_SMEM 98304

__global__ void __launch_bounds__(256, 1)
attn_mma_kernel(const __half* __restrict__ Qb, const __half* __restrict__ Kb,
                const __half* __restrict__ Vb, __half* __restrict__ Ph)
{
    extern __shared__ char smc[];
    const uint32_t sQ = smem_to_u32(smc);

    const int tid = threadIdx.x, w = tid >> 5, l = tid & 31;
    const int bid = blockIdx.x;
    const int bi  = 15 - (bid >> 5);       // q-tile index, heavy (15) first
    const int m   = bid & 31;
    const int q0  = bi * BM;
    const size_t mbase = (size_t)m * T_ * KD_;
    const int ntiles = 2 * bi + 2;

    // ---- prefetch K/V tile 0 into buf 0
    {
        const __half* ks = Kb + mbase;
        const __half* vs = Vb + mbase;
        #pragma unroll
        for (int it = 0; it < 4; it++) {
            int idx = it * 256 + tid;
            int r = idx >> 4, cb = idx & 15;
            int off = r * 256 + ((cb ^ (r & 7)) << 4);
            CP_ASYNC16(sQ + 32768 + off, ks + (size_t)r * KD_ + cb * 8);
            CP_ASYNC16(sQ + 49152 + off, vs + (size_t)r * KD_ + cb * 8);
        }
        CP_COMMIT();
    }

    // ---- load Q tile [128 x 128] into swizzled smem
    {
        const uint4* src = (const uint4*)(Qb + mbase + (size_t)q0 * KD_);
        #pragma unroll
        for (int it = 0; it < 8; it++) {
            int idx = it * 256 + tid;
            int r = idx >> 4, cb = idx & 15;
            uint4 v = src[idx];
            *(uint4*)(smc + r * 256 + ((cb ^ (r & 7)) << 4)) = v;
        }
    }
    __syncthreads();

    // ---- extract Q A-frags
    uint32_t qa[8][4];
    {
        const int mi = l >> 3;
        const int rr = w * 16 + (mi & 1) * 8 + (l & 7);
        #pragma unroll
        for (int kc = 0; kc < 8; kc++) {
            const int cb = kc * 2 + (mi >> 1);
            LDMATRIX_X4(qa[kc][0], qa[kc][1], qa[kc][2], qa[kc][3],
                        sQ + rr * 256 + ((cb ^ (rr & 7)) << 4));
        }
    }

    float oacc[16][4] = {};
    float lsum0 = 0.0f, lsum1 = 0.0f;
    const int r0g = q0 + w * 16 + (l >> 2);
    const int r1g = r0g + 8;

    for (int kt = 0; kt < ntiles; kt++) {
        __syncthreads();   // prior compute done (protects buf (kt+1)&1)
        if (kt + 1 < ntiles) {
            const int s1 = (kt + 1) * BN;
            const uint32_t base = sQ + 32768 + ((kt + 1) & 1) * 32768;
            const __half* ks = Kb + mbase + (size_t)s1 * KD_;
            const __half* vs = Vb + mbase + (size_t)s1 * KD_;
            #pragma unroll
            for (int it = 0; it < 4; it++) {
                int idx = it * 256 + tid;
                int r = idx >> 4, cb = idx & 15;
                int off = r * 256 + ((cb ^ (r & 7)) << 4);
                CP_ASYNC16(base + off,         ks + (size_t)r * KD_ + cb * 8);
                CP_ASYNC16(base + 16384 + off, vs + (size_t)r * KD_ + cb * 8);
            }
            CP_COMMIT();
            cp_wait<1>();
        } else {
            cp_wait<0>();
        }
        __syncthreads();

        const uint32_t sK = sQ + 32768 + (kt & 1) * 32768;
        const uint32_t sV = sK + 16384;
        const int s0 = kt * BN;

        // ---- S = Q K^T  (log2-domain logits)
        float sacc[8][4] = {};
        {
            const int mi = l >> 3;
            #pragma unroll
            for (int kc = 0; kc < 8; kc++) {
                #pragma unroll
                for (int j = 0; j < 8; j += 2) {
                    const int nr = (j + (mi >> 1)) * 8 + (l & 7);
                    const int cb = kc * 2 + (mi & 1);
                    uint32_t b0, b1, b2, b3;
                    LDMATRIX_X4(b0, b1, b2, b3, sK + nr * 256 + ((cb ^ (nr & 7)) << 4));
                    MMA_16816(sacc[j],     qa[kc], b0, b1);
                    MMA_16816(sacc[j + 1], qa[kc], b2, b3);
                }
            }
        }

        // ---- mask + ex2.f16x2 -> P A-frags (one MUFU per 2 values)
        uint32_t pa[4][4];
        {
            const int cb0 = s0 + 2 * (l & 3);
            #pragma unroll
            for (int j = 0; j < 8; j++) {
                const int c0 = cb0 + 8 * j, c1 = c0 + 1;
                float m00 = (c0 <= r0g) ? sacc[j][0] : -60.0f;
                float m01 = (c1 <= r0g) ? sacc[j][1] : -60.0f;
                float m10 = (c0 <= r1g) ? sacc[j][2] : -60.0f;
                float m11 = (c1 <= r1g) ? sacc[j][3] : -60.0f;
                __half2 ha = __floats2half2_rn(m00, m01);
                __half2 hb = __floats2half2_rn(m10, m11);
                uint32_t ua, ub;
                asm("ex2.approx.f16x2 %0, %1;" : "=r"(ua) : "r"(*(uint32_t*)&ha));
                asm("ex2.approx.f16x2 %0, %1;" : "=r"(ub) : "r"(*(uint32_t*)&hb));
                float2 fa = __half22float2(*(__half2*)&ua);
                float2 fb = __half22float2(*(__half2*)&ub);
                lsum0 += fa.x + fa.y;
                lsum1 += fb.x + fb.y;
                const int kc2 = j >> 1, hi = (j & 1) * 2;
                pa[kc2][hi + 0] = ua;
                pa[kc2][hi + 1] = ub;
            }
        }

        // ---- O += P V
        {
            const int mi = l >> 3;
            #pragma unroll
            for (int kc2 = 0; kc2 < 4; kc2++) {
                #pragma unroll
                for (int j = 0; j < 16; j += 2) {
                    const int sr = kc2 * 16 + (mi & 1) * 8 + (l & 7);
                    const int cb = j + (mi >> 1);
                    uint32_t b0, b1, b2, b3;
                    LDMATRIX_X4_T(b0, b1, b2, b3, sV + sr * 256 + ((cb ^ (sr & 7)) << 4));
                    MMA_16816(oacc[j],     pa[kc2], b0, b1);
                    MMA_16816(oacc[j + 1], pa[kc2], b2, b3);
                }
            }
        }
    }

    // ---- epilogue
    lsum0 += __shfl_xor_sync(0xffffffffu, lsum0, 1);
    lsum0 += __shfl_xor_sync(0xffffffffu, lsum0, 2);
    lsum1 += __shfl_xor_sync(0xffffffffu, lsum1, 1);
    lsum1 += __shfl_xor_sync(0xffffffffu, lsum1, 2);
    const float li0 = 1.0f / lsum0, li1 = 1.0f / lsum1;

    const int b = m >> 3, h = m & 7;
    __half* base0 = Ph + ((size_t)b * T_ + r0g) * C_ + h * KD_ + 2 * (l & 3);
    __half* base1 = Ph + ((size_t)b * T_ + r1g) * C_ + h * KD_ + 2 * (l & 3);
    #pragma unroll
    for (int j = 0; j < 16; j++) {
        *(__half2*)(base0 + 8 * j) = __floats2half2_rn(oacc[j][0] * li0, oacc[j][1] * li0);
        *(__half2*)(base1 + 8 * j) = __floats2half2_rn(oacc[j][2] * li1, oacc[j][3] * li1);
    }
}

// ===========================================================================
extern "C" void kernel_launch(void* const* d_in, const int* in_sizes, int n_in,
                              void* d_out, int out_size)
{
    const float* x  = (const float*)d_in[0];
    const float* Wq = (const float*)d_in[1];
    const float* bq = (const float*)d_in[2];
    const float* Wk = (const float*)d_in[3];
    const float* bk = (const float*)d_in[4];
    const float* Wv = (const float*)d_in[5];
    const float* Wu = (const float*)d_in[6];
    const float* bu = (const float*)d_in[7];
    float* out = (float*)d_out;

    __half *xh, *wq5, *wk5, *wv, *wu, *qp, *kp, *vp, *ph;
    float* pacc;
    cudaGetSymbolAddress((void**)&xh,   g_xh);
    cudaGetSymbolAddress((void**)&wq5,  g_Wq5);
    cudaGetSymbolAddress((void**)&wk5,  g_Wk5);
    cudaGetSymbolAddress((void**)&wv,   g_Wv);
    cudaGetSymbolAddress((void**)&wu,   g_Wu);
    cudaGetSymbolAddress((void**)&qp,   g_Qh);
    cudaGetSymbolAddress((void**)&kp,   g_Kh);
    cudaGetSymbolAddress((void**)&vp,   g_Vh);
    cudaGetSymbolAddress((void**)&ph,   g_Ph);
    cudaGetSymbolAddress((void**)&pacc, g_acc);

    cudaFuncSetAttribute(attn_mma_kernel, cudaFuncAttributeMaxDynamicSharedMemorySize, ATTN_SMEM);
    cudaFuncSetAttribute(qkvconv_kernel, cudaFuncAttributeMaxDynamicSharedMemorySize, QKV_SMEM);
    cudaFuncSetAttribute(proj_partial_kernel, cudaFuncAttributeMaxDynamicSharedMemorySize, 65536);

    // 1/128^0.25 * sqrt(log2(e))  -> S lands in log2 domain
    const float qk_scale = 0.3570958376f;

    // ---- fused prepack (1 launch)
    pack_all_kernel<<<N_PACK / 256, 256>>>(x, Wq, Wk, Wv, Wu, xh, wq5, wk5, wv, wu);

    // ---- merged Q/K/V conv (permuted weights -> coalesced epilogue)
    dim3 gqkv(T_ / 128, 24, B_);
    qkvconv_kernel<<<gqkv, 128, QKV_SMEM>>>(xh, wq5, wk5, wv, bq, bk, qp, kp, vp, qk_scale);

    // ---- attention (1D grid, heavy q-tiles first globally)
    attn_mma_kernel<<<512, 256, ATTN_SMEM>>>(qp, kp, vp, ph);

    // ---- output projection: split-K partials + reduce
    dim3 gp(T_ / 128, PSPLIT, B_);
    proj_partial_kernel<<<gp, 256, 65536>>>(ph, wu, pacc);
    proj_reduce_kernel<<<(B_ * T_ * KD_) / 256, 256>>>(pacc, bu, out);
}

// round 11
// speedup vs baseline: 13.2231x; 1.0385x over previous
#include <cuda_runtime.h>
#include <cuda_fp16.h>
#include <cstdint>
#include <cstddef>

// Problem constants
#define B_ 4
#define T_ 2048
#define KD_ 128
#define H_ 8
#define C_ 1024   // KD_*H_
#define PSPLIT 4

// Scratch (device globals; no allocation allowed)
__device__ __align__(256) __half g_xh [(size_t)B_ * T_ * KD_];    // x fp16 [b][t][cin]
__device__ __align__(256) __half g_Wq5[(size_t)5 * C_ * KD_];     // [tap][f(perm)][cin]
__device__ __align__(256) __half g_Wk5[(size_t)5 * C_ * KD_];
__device__ __align__(256) __half g_Wv [(size_t)C_ * KD_];         // [f(perm)][cin]
__device__ __align__(256) __half g_Wu [(size_t)KD_ * C_];         // [cout][f]
__device__ __align__(256) __half g_Qh [(size_t)32 * T_ * KD_];    // [b][t][f] == [m][t'][d]
__device__ __align__(256) __half g_Kh [(size_t)32 * T_ * KD_];
__device__ __align__(256) __half g_Vh [(size_t)32 * T_ * KD_];
__device__ __align__(256) __half g_Ph [(size_t)B_ * T_ * C_];     // attn out [b][t][f]
__device__ __align__(256) float  g_acc[(size_t)PSPLIT * B_ * T_ * KD_];  // proj partials

__device__ __forceinline__ uint32_t smem_to_u32(const void* p) {
    uint32_t a;
    asm("{ .reg .u64 t; cvta.to.shared.u64 t, %1; cvt.u32.u64 %0, t; }" : "=r"(a) : "l"(p));
    return a;
}

#define LDMATRIX_X4(r0, r1, r2, r3, addr) \
    asm volatile("ldmatrix.sync.aligned.m8n8.x4.shared.b16 {%0,%1,%2,%3}, [%4];" \
        : "=r"(r0), "=r"(r1), "=r"(r2), "=r"(r3) : "r"(addr))
#define LDMATRIX_X4_T(r0, r1, r2, r3, addr) \
    asm volatile("ldmatrix.sync.aligned.m8n8.x4.trans.shared.b16 {%0,%1,%2,%3}, [%4];" \
        : "=r"(r0), "=r"(r1), "=r"(r2), "=r"(r3) : "r"(addr))
#define MMA_16816(c, a, b0v, b1v) \
    asm volatile("mma.sync.aligned.m16n8k16.row.col.f32.f16.f16.f32 " \
        "{%0,%1,%2,%3},{%4,%5,%6,%7},{%8,%9},{%0,%1,%2,%3};" \
        : "+f"((c)[0]), "+f"((c)[1]), "+f"((c)[2]), "+f"((c)[3]) \
        : "r"((a)[0]), "r"((a)[1]), "r"((a)[2]), "r"((a)[3]), "r"(b0v), "r"(b1v))

#define CP_ASYNC16(dst, src) \
    asm volatile("cp.async.cg.shared.global [%0], [%1], 16;" :: "r"(dst), "l"(src))
#define CP_COMMIT() asm volatile("cp.async.commit_group;" ::: "memory")
template<int N> __device__ __forceinline__ void cp_wait() {
    asm volatile("cp.async.wait_group %0;" :: "n"(N) : "memory");
}

__device__ __forceinline__ float silu_f(float y) { return y / (1.0f + __expf(-y)); }

// ===========================================================================
// Fused prepack. Wq/Wk/Wv cout rows are PERMUTED: row f holds original
// channel c = ((f&127)<<3)|(f>>7)  (f = h*128 + k), so the conv's output
// channels come out directly in [b][t][f] order (coalesced stores).
// ===========================================================================
#define N_X  (B_ * T_ * KD_)        // 1048576
#define N_W5 (5 * C_ * KD_)         // 655360
#define N_WV (C_ * KD_)             // 131072
#define N_WU (KD_ * C_)             // 131072
#define N_PACK (N_X + 2 * N_W5 + N_WV + N_WU)

__global__ void pack_all_kernel(
    const float* __restrict__ x, const float* __restrict__ Wq,
    const float* __restrict__ Wk, const float* __restrict__ Wv,
    const float* __restrict__ Wu,
    __half* __restrict__ xh, __half* __restrict__ wq5, __half* __restrict__ wk5,
    __half* __restrict__ wv, __half* __restrict__ wu)
{
    int i = blockIdx.x * 256 + threadIdx.x;
    if (i < N_X) { xh[i] = __float2half(x[i]); return; }
    i -= N_X;
    if (i < N_W5) {
        int cin = i & 127, f = (i >> 7) & 1023, j = i >> 17;
        int c = ((f & 127) << 3) | (f >> 7);
        wq5[i] = __float2half(Wq[((c << 7) + cin) * 5 + j]);
        return;
    }
    i -= N_W5;
    if (i < N_W5) {
        int cin = i & 127, f = (i >> 7) & 1023, j = i >> 17;
        int c = ((f & 127) << 3) | (f >> 7);
        wk5[i] = __float2half(Wk[((c << 7) + cin) * 5 + j]);
        return;
    }
    i -= N_W5;
    if (i < N_WV) {
        int cin = i & 127, f = i >> 7;
        int c = ((f & 127) << 3) | (f >> 7);
        wv[i] = __float2half(Wv[(c << 7) + cin]);
        return;
    }
    i -= N_WV;
    if (i < N_WU) { wu[i] = __float2half(Wu[i]); }
}

// ===========================================================================
// Merged Q/K/V conv kernel. 128 threads / 4 warps, M=32 rows per warp.
// A-resident, B double-buffered cp.async over taps; permuted weights give
// COALESCED __half2 epilogue stores into [b][t][f].
// blockIdx.y: 0-7 Q tiles, 8-15 K tiles, 16-23 V tiles (1 tap, row off 8).
// ===========================================================================
#define QKV_SMEM (34816 + 2 * 32768)

__global__ void __launch_bounds__(128, 2) qkvconv_kernel(
    const __half* __restrict__ A,
    const __half* __restrict__ Wq5, const __half* __restrict__ Wk5,
    const __half* __restrict__ Wv,
    const float* __restrict__ bq, const float* __restrict__ bk,
    __half* __restrict__ Qo, __half* __restrict__ Ko, __half* __restrict__ Vo,
    float qk_scale)
{
    extern __shared__ char smc[];
    const uint32_t sA  = smem_to_u32(smc);
    const uint32_t sB0 = sA + 34816;

    const int t0 = blockIdx.x * 128;
    const int cm = blockIdx.y;
    const int mat = cm >> 3;                 // 0=Q 1=K 2=V
    const int c0 = (cm & 7) * 128;           // f-tile base
    const int b  = blockIdx.z;
    const __half* Bw  = (mat == 0) ? Wq5 : (mat == 1) ? Wk5 : Wv;
    const float* bias = (mat == 0) ? bq  : (mat == 1) ? bk  : nullptr;
    __half* out       = (mat == 0) ? Qo  : (mat == 1) ? Ko  : Vo;
    const float scale = (mat == 2) ? 1.0f : qk_scale;
    const int ntaps   = (mat == 2) ? 1 : 5;

    const int tid = threadIdx.x, w = tid >> 5, l = tid & 31;
    const int mi = l >> 3;

    // ---- prefetch B tap 0 into buf 0 (32KB / 128 thr = 16 x 16B each)
    #pragma unroll
    for (int it = 0; it < 16; it++) {
        int idx = it * 128 + tid;
        int r = idx >> 4, cb = idx & 15;
        CP_ASYNC16(sB0 + r * 256 + ((cb ^ (r & 7)) << 4),
                   Bw + ((size_t)(c0 + r)) * 128 + cb * 8);
    }
    CP_COMMIT();

    // ---- load A rows t0-8 .. t0+127 (136 rows), guarded
    #pragma unroll
    for (int it = 0; it < 17; it++) {
        int idx = it * 128 + tid;
        if (idx < 136 * 16) {
            int r = idx >> 4, cb = idx & 15;
            int tg = t0 + r - 8;
            uint4 v = make_uint4(0u, 0u, 0u, 0u);
            if (tg >= 0 && tg < T_)
                v = *(const uint4*)(A + ((size_t)b * T_ + tg) * 128 + cb * 8);
            *(uint4*)(smc + r * 256 + ((cb ^ (r & 7)) << 4)) = v;
        }
    }

    float cacc[2][16][4] = {};

    #pragma unroll 1
    for (int j = 0; j < ntaps; j++) {
        __syncthreads();   // prior compute done (protects buf (j+1)&1); A stores for j=0
        if (j + 1 < ntaps) {
            const uint32_t sBn = sB0 + ((j + 1) & 1) * 32768;
            #pragma unroll
            for (int it = 0; it < 16; it++) {
                int idx = it * 128 + tid;
                int r = idx >> 4, cb = idx & 15;
                CP_ASYNC16(sBn + r * 256 + ((cb ^ (r & 7)) << 4),
                           Bw + ((size_t)(j + 1) * C_ + c0 + r) * 128 + cb * 8);
            }
            CP_COMMIT();
            cp_wait<1>();
        } else {
            cp_wait<0>();
        }
        __syncthreads();

        const uint32_t sB = sB0 + (j & 1) * 32768;
        const int rowoff = (mat == 2) ? 8 : 2 * j;  // A row = out row + rowoff
        #pragma unroll
        for (int kc = 0; kc < 8; kc++) {
            uint32_t a4[2][4];
            #pragma unroll
            for (int rg = 0; rg < 2; rg++) {
                const int rr = w * 32 + rg * 16 + (mi & 1) * 8 + (l & 7) + rowoff;
                const int cba = kc * 2 + (mi >> 1);
                LDMATRIX_X4(a4[rg][0], a4[rg][1], a4[rg][2], a4[rg][3],
                            sA + rr * 256 + ((cba ^ (rr & 7)) << 4));
            }
            #pragma unroll
            for (int jn = 0; jn < 16; jn += 2) {
                const int nr = (jn + (mi >> 1)) * 8 + (l & 7);
                const int cbb = kc * 2 + (mi & 1);
                uint32_t b0, b1, b2, b3;
                LDMATRIX_X4(b0, b1, b2, b3, sB + nr * 256 + ((cbb ^ (nr & 7)) << 4));
                MMA_16816(cacc[0][jn],     a4[0], b0, b1);
                MMA_16816(cacc[0][jn + 1], a4[0], b2, b3);
                MMA_16816(cacc[1][jn],     a4[1], b0, b1);
                MMA_16816(cacc[1][jn + 1], a4[1], b2, b3);
            }
        }
    }

    // ---- epilogue: bias(perm) + silu + scale, COALESCED half2 stores [b][t][f]
    #pragma unroll
    for (int rg = 0; rg < 2; rg++) {
        const int tr0 = t0 + w * 32 + rg * 16 + (l >> 2);
        const int tr1 = tr0 + 8;
        #pragma unroll
        for (int jn = 0; jn < 16; jn++) {
            const int f = c0 + 8 * jn + 2 * (l & 3);
            float bv0 = 0.0f, bv1 = 0.0f;
            if (mat < 2) {
                const int co = ((f & 127) << 3) | (f >> 7);   // original channel
                bv0 = bias[co];
                bv1 = bias[co + 8];                            // f+1 -> k+1 -> c+8
            }
            float s00 = silu_f(cacc[rg][jn][0] + bv0) * scale;
            float s01 = silu_f(cacc[rg][jn][1] + bv1) * scale;
            float s10 = silu_f(cacc[rg][jn][2] + bv0) * scale;
            float s11 = silu_f(cacc[rg][jn][3] + bv1) * scale;
            *(__half2*)(out + ((size_t)b * T_ + tr0) * C_ + f) = __floats2half2_rn(s00, s01);
            *(__half2*)(out + ((size_t)b * T_ + tr1) * C_ + f) = __floats2half2_rn(s10, s11);
        }
    }
}

// ===========================================================================
// Projection with split-K: partial GEMM (no act) + reduce(bias+silu).
// Both K-chunks prefetched via cp.async at CTA start (2 groups, 128KB smem).
// ===========================================================================
#define PROJ_SMEM 131072

__global__ void __launch_bounds__(256, 1) proj_partial_kernel(
    const __half* __restrict__ A, const __half* __restrict__ Bw,
    float* __restrict__ part)
{
    extern __shared__ char smc[];
    const uint32_t sBase = smem_to_u32(smc);

    const int t0 = blockIdx.x * 128;
    const int sp = blockIdx.y;
    const int b  = blockIdx.z;
    const int tid = threadIdx.x, w = tid >> 5, l = tid & 31;
    const int mi = l >> 3;

    // ---- prefetch both chunks (A tile + B tile per chunk, one group each)
    #pragma unroll
    for (int ch = 0; ch < 2; ch++) {
        const int cin0 = sp * 256 + ch * 128;
        const uint32_t sA = sBase + ch * 65536;
        const uint32_t sB = sA + 32768;
        #pragma unroll
        for (int it = 0; it < 8; it++) {
            int idx = it * 256 + tid;
            int r = idx >> 4, cb = idx & 15;
            int off = r * 256 + ((cb ^ (r & 7)) << 4);
            CP_ASYNC16(sA + off, A + ((size_t)b * T_ + t0 + r) * C_ + cin0 + cb * 8);
            CP_ASYNC16(sB + off, Bw + (size_t)r * C_ + cin0 + cb * 8);
        }
        CP_COMMIT();
    }

    float cacc[16][4] = {};

    #pragma unroll
    for (int ch = 0; ch < 2; ch++) {
        if (ch == 0) cp_wait<1>(); else cp_wait<0>();
        __syncthreads();
        const uint32_t sA = sBase + ch * 65536;
        const uint32_t sB = sA + 32768;
        #pragma unroll
        for (int kc = 0; kc < 8; kc++) {
            uint32_t a4[4];
            const int rr = w * 16 + (mi & 1) * 8 + (l & 7);
            const int cba = kc * 2 + (mi >> 1);
            LDMATRIX_X4(a4[0], a4[1], a4[2], a4[3],
                        sA + rr * 256 + ((cba ^ (rr & 7)) << 4));
            #pragma unroll
            for (int jn = 0; jn < 16; jn += 2) {
                const int nr = (jn + (mi >> 1)) * 8 + (l & 7);
                const int cbb = kc * 2 + (mi & 1);
                uint32_t b0, b1, b2, b3;
                LDMATRIX_X4(b0, b1, b2, b3, sB + nr * 256 + ((cbb ^ (nr & 7)) << 4));
                MMA_16816(cacc[jn],     a4, b0, b1);
                MMA_16816(cacc[jn + 1], a4, b2, b3);
            }
        }
    }

    const int tr0 = t0 + w * 16 + (l >> 2);
    const int tr1 = tr0 + 8;
    float* dst = part + (size_t)sp * (B_ * T_ * KD_);
    #pragma unroll
    for (int jn = 0; jn < 16; jn++) {
        const int c = 8 * jn + 2 * (l & 3);
        *(float2*)(dst + ((size_t)b * T_ + tr0) * KD_ + c) = make_float2(cacc[jn][0], cacc[jn][1]);
        *(float2*)(dst + ((size_t)b * T_ + tr1) * KD_ + c) = make_float2(cacc[jn][2], cacc[jn][3]);
    }
}

__global__ void proj_reduce_kernel(const float* __restrict__ part,
                                   const float* __restrict__ bu,
                                   float* __restrict__ out)
{
    const int i = blockIdx.x * 256 + threadIdx.x;   // over B*T*128
    const int c = i & 127;
    const int S = B_ * T_ * KD_;
    float s = part[i] + part[i + S] + part[i + 2 * S] + part[i + 3 * S];
    out[i] = silu_f(s + bu[c]);
}

// ===========================================================================
// Flash attention via mma.sync; K/V loaded in PAIRS of s-tiles per cp.async
// group (ntiles = 2*bi+2 is always even) -> half the syncs/prefetch rounds.
// Q/K carry sqrt(log2e) factor -> S in log2 domain; exp via ex2.f16x2.
// Smem: Q 32KB | buf0 [K 32KB | V 32KB] | buf1 [K 32KB | V 32KB] = 160KB.
// ===========================================================================
#define BM 128
#define BN 64
#define ATTN_SMEM (32768 + 2 * 65536)

__global__ void __launch_bounds__(256, 1)
attn_mma_kernel(const __half* __restrict__ Qb, const __half* __restrict__ Kb,
                const __half* __restrict__ Vb, __half* __restrict__ Ph)
{
    extern __shared__ char smc[];
    const uint32_t sQ = smem_to_u32(smc);

    const int tid = threadIdx.x, w = tid >> 5, l = tid & 31;
    const int bid = blockIdx.x;
    const int bi  = 15 - (bid >> 5);       // q-tile index, heavy (15) first
    const int m   = bid & 31;
    const int q0  = bi * BM;
    const size_t mbase = (size_t)m * T_ * KD_;
    const int npairs = bi + 1;             // (2*bi+2)/2 pairs of 64-row s-tiles

    // ---- prefetch pair 0 (128 K rows + 128 V rows) into buf 0
    {
        const __half* ks = Kb + mbase;
        const __half* vs = Vb + mbase;
        #pragma unroll
        for (int it = 0; it < 8; it++) {
            int idx = it * 256 + tid;
            int r = idx >> 4, cb = idx & 15;
            int off = r * 256 + ((cb ^ (r & 7)) << 4);
            CP_ASYNC16(sQ + 32768 + off,         ks + (size_t)r * KD_ + cb * 8);
            CP_ASYNC16(sQ + 32768 + 32768 + off, vs + (size_t)r * KD_ + cb * 8);
        }
        CP_COMMIT();
    }

    // ---- load Q tile [128 x 128] into swizzled smem
    {
        const uint4* src = (const uint4*)(Qb + mbase + (size_t)q0 * KD_);
        #pragma unroll
        for (int it = 0; it < 8; it++) {
            int idx = it * 256 + tid;
            int r = idx >> 4, cb = idx & 15;
            uint4 v = src[idx];
            *(uint4*)(smc + r * 256 + ((cb ^ (r & 7)) << 4)) = v;
        }
    }
    __syncthreads();

    // ---- extract Q A-frags
    uint32_t qa[8][4];
    {
        const int mi = l >> 3;
        const int rr = w * 16 + (mi & 1) * 8 + (l & 7);
        #pragma unroll
        for (int kc = 0; kc < 8; kc++) {
            const int cb = kc * 2 + (mi >> 1);
            LDMATRIX_X4(qa[kc][0], qa[kc][1], qa[kc][2], qa[kc][3],
                        sQ + rr * 256 + ((cb ^ (rr & 7)) << 4));
        }
    }

    float oacc[16][4] = {};
    float lsum0 = 0.0f, lsum1 = 0.0f;
    const int r0g = q0 + w * 16 + (l >> 2);
    const int r1g = r0g + 8;

    #pragma unroll 1
    for (int p = 0; p < npairs; p++) {
        __syncthreads();   // prior compute done (protects buf (p+1)&1)
        if (p + 1 < npairs) {
            const int s1 = (p + 1) * 128;
            const uint32_t base = sQ + 32768 + ((p + 1) & 1) * 65536;
            const __half* ks = Kb + mbase + (size_t)s1 * KD_;
            const __half* vs = Vb + mbase + (size_t)s1 * KD_;
            #pragma unroll
            for (int it = 0; it < 8; it++) {
                int idx = it * 256 + tid;
                int r = idx >> 4, cb = idx & 15;
                int off = r * 256 + ((cb ^ (r & 7)) << 4);
                CP_ASYNC16(base + off,         ks + (size_t)r * KD_ + cb * 8);
                CP_ASYNC16(base + 32768 + off, vs + (size_t)r * KD_ + cb * 8);
            }
            CP_COMMIT();
            cp_wait<1>();
        } else {
            cp_wait<0>();
        }
        __syncthreads();

        const uint32_t bufK = sQ + 32768 + (p & 1) * 65536;
        const uint32_t bufV = bufK + 32768;

        #pragma unroll
        for (int sub = 0; sub < 2; sub++) {
            const int s0 = p * 128 + sub * BN;
            const uint32_t sK = bufK + sub * 64 * 256;
            const uint32_t sV = bufV + sub * 64 * 256;

            // ---- S = Q K^T  (log2-domain logits)
            float sacc[8][4] = {};
            {
                const int mi = l >> 3;
                #pragma unroll
                for (int kc = 0; kc < 8; kc++) {
                    #pragma unroll
                    for (int j = 0; j < 8; j += 2) {
                        const int nr = (j + (mi >> 1)) * 8 + (l & 7);
                        const int cb = kc * 2 + (mi & 1);
                        uint32_t b0, b1, b2, b3;
                        LDMATRIX_X4(b0, b1, b2, b3, sK + nr * 256 + ((cb ^ (nr & 7)) << 4));
                        MMA_16816(sacc[j],     qa[kc], b0, b1);
                        MMA_16816(sacc[j + 1], qa[kc], b2, b3);
                    }
                }
            }

            // ---- mask + ex2.f16x2 -> P A-frags (one MUFU per 2 values)
            uint32_t pa[4][4];
            {
                const int cb0 = s0 + 2 * (l & 3);
                #pragma unroll
                for (int j = 0; j < 8; j++) {
                    const int c0 = cb0 + 8 * j, c1 = c0 + 1;
                    float m00 = (c0 <= r0g) ? sacc[j][0] : -60.0f;
                    float m01 = (c1 <= r0g) ? sacc[j][1] : -60.0f;
                    float m10 = (c0 <= r1g) ? sacc[j][2] : -60.0f;
                    float m11 = (c1 <= r1g) ? sacc[j][3] : -60.0f;
                    __half2 ha = __floats2half2_rn(m00, m01);
                    __half2 hb = __floats2half2_rn(m10, m11);
                    uint32_t ua, ub;
                    asm("ex2.approx.f16x2 %0, %1;" : "=r"(ua) : "r"(*(uint32_t*)&ha));
                    asm("ex2.approx.f16x2 %0, %1;" : "=r"(ub) : "r"(*(uint32_t*)&hb));
                    float2 fa = __half22float2(*(__half2*)&ua);
                    float2 fb = __half22float2(*(__half2*)&ub);
                    lsum0 += fa.x + fa.y;
                    lsum1 += fb.x + fb.y;
                    const int kc2 = j >> 1, hi = (j & 1) * 2;
                    pa[kc2][hi + 0] = ua;
                    pa[kc2][hi + 1] = ub;
                }
            }

            // ---- O += P V
            {
                const int mi = l >> 3;
                #pragma unroll
                for (int kc2 = 0; kc2 < 4; kc2++) {
                    #pragma unroll
                    for (int j = 0; j < 16; j += 2) {
                        const int sr = kc2 * 16 + (mi & 1) * 8 + (l & 7);
                        const int cb = j + (mi >> 1);
                        uint32_t b0, b1, b2, b3;
                        LDMATRIX_X4_T(b0, b1, b2, b3, sV + sr * 256 + ((cb ^ (sr & 7)) << 4));
                        MMA_16816(oacc[j],     pa[kc2], b0, b1);
                        MMA_16816(oacc[j + 1], pa[kc2], b2, b3);
                    }
                }
            }
        }
    }

    // ---- epilogue
    lsum0 += __shfl_xor_sync(0xffffffffu, lsum0, 1);
    lsum0 += __shfl_xor_sync(0xffffffffu, lsum0, 2);
    lsum1 += __shfl_xor_sync(0xffffffffu, lsum1, 1);
    lsum1 += __shfl_xor_sync(0xffffffffu, lsum1, 2);
    const float li0 = 1.0f / lsum0, li1 = 1.0f / lsum1;

    const int b = m >> 3, h = m & 7;
    __half* base0 = Ph + ((size_t)b * T_ + r0g) * C_ + h * KD_ + 2 * (l & 3);
    __half* base1 = Ph + ((size_t)b * T_ + r1g) * C_ + h * KD_ + 2 * (l & 3);
    #pragma unroll
    for (int j = 0; j < 16; j++) {
        *(__half2*)(base0 + 8 * j) = __floats2half2_rn(oacc[j][0] * li0, oacc[j][1] * li0);
        *(__half2*)(base1 + 8 * j) = __floats2half2_rn(oacc[j][2] * li1, oacc[j][3] * li1);
    }
}

// ===========================================================================
extern "C" void kernel_launch(void* const* d_in, const int* in_sizes, int n_in,
                              void* d_out, int out_size)
{
    const float* x  = (const float*)d_in[0];
    const float* Wq = (const float*)d_in[1];
    const float* bq = (const float*)d_in[2];
    const float* Wk = (const float*)d_in[3];
    const float* bk = (const float*)d_in[4];
    const float* Wv = (const float*)d_in[5];
    const float* Wu = (const float*)d_in[6];
    const float* bu = (const float*)d_in[7];
    float* out = (float*)d_out;

    __half *xh, *wq5, *wk5, *wv, *wu, *qp, *kp, *vp, *ph;
    float* pacc;
    cudaGetSymbolAddress((void**)&xh,   g_xh);
    cudaGetSymbolAddress((void**)&wq5,  g_Wq5);
    cudaGetSymbolAddress((void**)&wk5,  g_Wk5);
    cudaGetSymbolAddress((void**)&wv,   g_Wv);
    cudaGetSymbolAddress((void**)&wu,   g_Wu);
    cudaGetSymbolAddress((void**)&qp,   g_Qh);
    cudaGetSymbolAddress((void**)&kp,   g_Kh);
    cudaGetSymbolAddress((void**)&vp,   g_Vh);
    cudaGetSymbolAddress((void**)&ph,   g_Ph);
    cudaGetSymbolAddress((void**)&pacc, g_acc);

    cudaFuncSetAttribute(attn_mma_kernel, cudaFuncAttributeMaxDynamicSharedMemorySize, ATTN_SMEM);
    cudaFuncSetAttribute(qkvconv_kernel, cudaFuncAttributeMaxDynamicSharedMemorySize, QKV_SMEM);
    cudaFuncSetAttribute(proj_partial_kernel, cudaFuncAttributeMaxDynamicSharedMemorySize, PROJ_SMEM);

    // 1/128^0.25 * sqrt(log2(e))  -> S lands in log2 domain
    const float qk_scale = 0.3570958376f;

    // ---- fused prepack (1 launch)
    pack_all_kernel<<<N_PACK / 256, 256>>>(x, Wq, Wk, Wv, Wu, xh, wq5, wk5, wv, wu);

    // ---- merged Q/K/V conv (permuted weights -> coalesced epilogue)
    dim3 gqkv(T_ / 128, 24, B_);
    qkvconv_kernel<<<gqkv, 128, QKV_SMEM>>>(xh, wq5, wk5, wv, bq, bk, qp, kp, vp, qk_scale);

    // ---- attention (1D grid, heavy q-tiles first globally)
    attn_mma_kernel<<<512, 256, ATTN_SMEM>>>(qp, kp, vp, ph);

    // ---- output projection: split-K partials + reduce
    dim3 gp(T_ / 128, PSPLIT, B_);
    proj_partial_kernel<<<gp, 256, PROJ_SMEM>>>(ph, wu, pacc);
    proj_reduce_kernel<<<(B_ * T_ * KD_) / 256, 256>>>(pacc, bu, out);
}